// round 1
// baseline (speedup 1.0000x reference)
#include <cuda_runtime.h>
#include <cuda_bf16.h>
#include <math.h>

// Problem constants
#define BB 16
#define QQ 50
#define GG 16
#define PP 64
#define NT 7

// Scratch (device globals: no allocation allowed)
__device__ float g_curve[BB * QQ * GG];
__device__ float g_dir[BB * QQ * GG];
__device__ float g_cost[BB * QQ * GG];
__device__ int   g_match[BB * GG];   // g_match[b*G+g] = matched pred row q
__device__ float g_pair[BB * GG];    // weighted per-pair loss

// ---------------------------------------------------------------------------
// Kernel A: cost matrix. One block per (b,q,g), 64 threads (one per point).
// ---------------------------------------------------------------------------
__global__ void cost_kernel(const float* __restrict__ pred_pts,
                            const float* __restrict__ gt_pts,
                            const float* __restrict__ gt_vis,
                            const float* __restrict__ pred_exist)
{
    int blk = blockIdx.x;
    int g = blk % GG;
    int q = (blk / GG) % QQ;
    int b = blk / (GG * QQ);
    int t = threadIdx.x;   // 0..63

    __shared__ float2 sP[PP], sG[PP];
    __shared__ float  sV[PP];
    __shared__ float2 sAbP[PP - 1], sAbG[PP - 1];
    __shared__ float  sIdP[PP - 1], sIdG[PP - 1];
    __shared__ float2 sTp[PP - 1], sTg[PP - 1];
    __shared__ float  red[5][PP];

    const float* pp = pred_pts + ((size_t)(b * QQ + q)) * PP * 2;
    const float* gp = gt_pts   + ((size_t)(b * GG + g)) * PP * 2;
    sP[t] = make_float2(pp[2 * t], pp[2 * t + 1]);
    sG[t] = make_float2(gp[2 * t], gp[2 * t + 1]);
    sV[t] = gt_vis[(size_t)(b * GG + g) * PP + t];
    __syncthreads();

    if (t < PP - 1) {
        float2 abp = make_float2(sP[t + 1].x - sP[t].x, sP[t + 1].y - sP[t].y);
        sAbP[t] = abp;
        float dp = abp.x * abp.x + abp.y * abp.y;
        sIdP[t] = 1.0f / fmaxf(dp, 1e-8f);
        float npn = fmaxf(sqrtf(dp), 1e-6f);
        sTp[t] = make_float2(abp.x / npn, abp.y / npn);

        float2 abg = make_float2(sG[t + 1].x - sG[t].x, sG[t + 1].y - sG[t].y);
        sAbG[t] = abg;
        float dg = abg.x * abg.x + abg.y * abg.y;
        sIdG[t] = 1.0f / fmaxf(dg, 1e-8f);
        float ngn = fmaxf(sqrtf(dg), 1e-6f);
        sTg[t] = make_float2(abg.x / ngn, abg.y / ngn);
    }
    __syncthreads();

    // min over segments of squared distance (sqrt is monotone; apply once at end)
    float2 p  = sP[t];   // pred point t vs gt segments
    float2 gq = sG[t];   // gt point t vs pred segments
    float m1 = 3.0e38f, m2 = 3.0e38f;
    #pragma unroll 4
    for (int j = 0; j < PP - 1; j++) {
        // p2g
        {
            float2 a = sG[j]; float2 ab = sAbG[j];
            float apx = p.x - a.x, apy = p.y - a.y;
            float tt = __saturatef((apx * ab.x + apy * ab.y) * sIdG[j]);
            float dx = apx - tt * ab.x, dy = apy - tt * ab.y;
            m1 = fminf(m1, dx * dx + dy * dy);
        }
        // g2p
        {
            float2 a = sP[j]; float2 ab = sAbP[j];
            float apx = gq.x - a.x, apy = gq.y - a.y;
            float tt = __saturatef((apx * ab.x + apy * ab.y) * sIdP[j]);
            float dx = apx - tt * ab.x, dy = apy - tt * ab.y;
            m2 = fminf(m2, dx * dx + dy * dy);
        }
    }
    float dp2g = sqrtf(fmaxf(m1, 1e-24f));
    float visv = sV[t];
    float dg2p = sqrtf(fmaxf(m2, 1e-24f)) * visv;

    float dnum = 0.0f, dden = 0.0f;
    if (t < PP - 1) {
        float sv = sV[t] * sV[t + 1];
        float dot = sTp[t].x * sTg[t].x + sTp[t].y * sTg[t].y;
        dnum = (1.0f - dot) * sv;
        dden = sv;
    }

    red[0][t] = dp2g; red[1][t] = dg2p; red[2][t] = visv;
    red[3][t] = dnum; red[4][t] = dden;
    __syncthreads();
    for (int s = 32; s > 0; s >>= 1) {
        if (t < s) {
            #pragma unroll
            for (int k = 0; k < 5; k++) red[k][t] += red[k][t + s];
        }
        __syncthreads();
    }

    if (t == 0) {
        float visS = fmaxf(red[2][0], 1.0f);
        float curve = 0.5f * (red[0][0] * (1.0f / PP) + red[1][0] / visS);
        float dir = red[3][0] / fmaxf(red[4][0], 1.0f);
        int idx = (b * QQ + q) * GG + g;
        g_curve[idx] = curve;
        g_dir[idx] = dir;
        float x = pred_exist[b * QQ + q];
        float sig = 1.0f / (1.0f + expf(-x));
        g_cost[idx] = curve + 0.35f * dir - 0.25f * sig;
    }
}

// ---------------------------------------------------------------------------
// Kernel B: rectangular Hungarian (JV), rows = G gt lanes, cols = Q preds.
// One warp per batch. Equivalent to the reference's padded-square solve
// (pad columns have constant cost => identical real matching).
// ---------------------------------------------------------------------------
__global__ void hungarian_kernel()
{
    int b = blockIdx.x;
    int lane = threadIdx.x;  // 0..31

    __shared__ double sC[GG][QQ];
    __shared__ double su[GG + 1], sv[QQ + 1], sminv[QQ + 1];
    __shared__ int sway[QQ + 1], sp[QQ + 1];
    __shared__ int sused[QQ + 1];

    for (int idx = lane; idx < GG * QQ; idx += 32) {
        int gg = idx / QQ, qq = idx % QQ;
        sC[gg][qq] = (double)g_cost[(b * QQ + qq) * GG + gg];
    }
    for (int j = lane; j <= QQ; j += 32) { sv[j] = 0.0; sp[j] = 0; }
    for (int i = lane; i <= GG; i += 32) su[i] = 0.0;
    __syncwarp();

    const double INF = 1e18;

    for (int i = 1; i <= GG; ++i) {
        if (lane == 0) sp[0] = i;
        for (int j = lane; j <= QQ; j += 32) { sminv[j] = INF; sused[j] = 0; }
        __syncwarp();
        int j0 = 0;
        while (true) {
            if (lane == 0) sused[j0] = 1;
            __syncwarp();
            int i0 = sp[j0];
            double ui0 = su[i0];

            double best = 1e30; int bestj = QQ + 1;
            for (int j = lane + 1; j <= QQ; j += 32) {
                if (!sused[j]) {
                    double cur = sC[i0 - 1][j - 1] - ui0 - sv[j];
                    if (cur < sminv[j]) { sminv[j] = cur; sway[j] = j0; }
                    double mv = sminv[j];
                    if (mv < best) { best = mv; bestj = j; }  // ascending j -> ties keep lowest
                }
            }
            // warp argmin with lowest-index tie-break (matches np.argmin)
            #pragma unroll
            for (int off = 16; off > 0; off >>= 1) {
                double ob = __shfl_down_sync(0xffffffffu, best, off);
                int oj = __shfl_down_sync(0xffffffffu, bestj, off);
                if (ob < best || (ob == best && oj < bestj)) { best = ob; bestj = oj; }
            }
            best = __shfl_sync(0xffffffffu, best, 0);
            bestj = __shfl_sync(0xffffffffu, bestj, 0);
            double delta = best;
            __syncwarp();
            for (int j = lane; j <= QQ; j += 32) {
                if (sused[j]) { su[sp[j]] += delta; sv[j] -= delta; }
                else           sminv[j] -= delta;
            }
            j0 = bestj;
            __syncwarp();
            if (sp[j0] == 0) break;
        }
        __syncwarp();
        if (lane == 0) {
            int jj = j0;
            while (jj) { int jn = sway[jj]; sp[jj] = sp[jn]; jj = jn; }
        }
        __syncwarp();
    }

    for (int j = lane + 1; j <= QQ; j += 32) {
        int r = sp[j];
        if (r > 0) g_match[b * GG + (r - 1)] = j - 1;
    }
}

// ---------------------------------------------------------------------------
// Kernel C: matched-pair losses. curve/dir reused from the cost pass.
// One block per (b,g), 64 threads.
// ---------------------------------------------------------------------------
__device__ __forceinline__ float smooth_l1(float x) {
    float ax = fabsf(x);
    return (ax < 1.0f) ? 0.5f * x * x : ax - 0.5f;
}

__global__ void pair_kernel(const float* __restrict__ pred_pts,
                            const float* __restrict__ gt_pts,
                            const float* __restrict__ gt_vis,
                            const float* __restrict__ pred_type,
                            const int* __restrict__ gt_type)
{
    int pair = blockIdx.x;
    int b = pair / GG, g = pair % GG;
    int t = threadIdx.x;

    __shared__ int s_row;
    if (t == 0) s_row = g_match[pair];
    __syncthreads();
    int row = s_row;

    __shared__ float2 sP[PP], sG[PP];
    __shared__ float sV[PP];
    __shared__ float red[4][PP];

    const float* pp = pred_pts + ((size_t)(b * QQ + row)) * PP * 2;
    const float* gp = gt_pts   + ((size_t)(b * GG + g)) * PP * 2;
    sP[t] = make_float2(pp[2 * t], pp[2 * t + 1]);
    sG[t] = make_float2(gp[2 * t], gp[2 * t + 1]);
    sV[t] = gt_vis[(size_t)(b * GG + g) * PP + t];
    __syncthreads();

    float v = sV[t];
    float ptsv = (smooth_l1(sP[t].x - sG[t].x) + smooth_l1(sP[t].y - sG[t].y)) * v;

    float smv = 0.0f, cvv = 0.0f;
    if (t >= 1 && t <= PP - 2) {
        float sx = sP[t + 1].x - 2.0f * sP[t].x + sP[t - 1].x;
        float sy = sP[t + 1].y - 2.0f * sP[t].y + sP[t - 1].y;
        float mag = sqrtf(fmaxf(sx * sx + sy * sy, 1e-24f));
        float cv = sV[t - 1] * sV[t] * sV[t + 1];
        smv = mag * cv;
        cvv = cv;
    }

    red[0][t] = ptsv; red[1][t] = v; red[2][t] = smv; red[3][t] = cvv;
    __syncthreads();
    for (int s = 32; s > 0; s >>= 1) {
        if (t < s) {
            #pragma unroll
            for (int k = 0; k < 4; k++) red[k][t] += red[k][t + s];
        }
        __syncthreads();
    }

    if (t == 0) {
        float visS = fmaxf(red[1][0], 1.0f);
        float pts = red[0][0] / visS;
        float smooth = red[2][0] / fmaxf(red[3][0], 1.0f);

        const float* lg = pred_type + (size_t)(b * QQ + row) * NT;
        int label = gt_type[b * GG + g];
        float mx = lg[0];
        #pragma unroll
        for (int k = 1; k < NT; k++) mx = fmaxf(mx, lg[k]);
        float se = 0.0f;
        #pragma unroll
        for (int k = 0; k < NT; k++) se += expf(lg[k] - mx);
        float ce = mx + logf(se) - lg[label];

        int ci = (b * QQ + row) * GG + g;
        float curve = g_curve[ci];
        float dir = g_dir[ci];

        // PTS_W=3, CURVE_W=5, DIR_W=1.5, SMOOTH_W=0.25, TYPE_W=0.5
        g_pair[pair] = 3.0f * pts + 5.0f * curve + 1.5f * dir +
                       0.25f * smooth + 0.5f * ce;
    }
}

// ---------------------------------------------------------------------------
// Kernel D: final deterministic reduction (pair sum + exist BCE) -> scalar.
// ---------------------------------------------------------------------------
__global__ void final_kernel(const float* __restrict__ pred_exist,
                             float* __restrict__ out)
{
    int t = threadIdx.x;  // 0..255
    __shared__ float sa[256], sb[256];

    float pacc = g_pair[t];  // exactly 256 pairs

    float bacc = 0.0f;
    for (int idx = t; idx < BB * QQ; idx += 256) {
        int b = idx / QQ, q = idx % QQ;
        float tgt = 0.0f;
        #pragma unroll
        for (int k = 0; k < GG; k++)
            if (g_match[b * GG + k] == q) tgt = 1.0f;
        float x = pred_exist[idx];
        bacc += fmaxf(x, 0.0f) - x * tgt + log1pf(expf(-fabsf(x)));
    }

    sa[t] = pacc; sb[t] = bacc;
    __syncthreads();
    for (int s = 128; s > 0; s >>= 1) {
        if (t < s) { sa[t] += sa[t + s]; sb[t] += sb[t + s]; }
        __syncthreads();
    }
    if (t == 0) {
        float bce = sb[0] / (float)(BB * QQ);
        out[0] = 1.5f * bce + sa[0] / (float)(BB * GG);
    }
}

// ---------------------------------------------------------------------------
extern "C" void kernel_launch(void* const* d_in, const int* in_sizes, int n_in,
                              void* d_out, int out_size)
{
    const float* pred_exist = (const float*)d_in[0];
    const float* pred_pts   = (const float*)d_in[1];
    const float* pred_type  = (const float*)d_in[2];
    const float* gt_points  = (const float*)d_in[4];
    const float* gt_vis     = (const float*)d_in[5];
    const int*   gt_type    = (const int*)d_in[6];
    float* out = (float*)d_out;

    cost_kernel<<<BB * QQ * GG, PP>>>(pred_pts, gt_points, gt_vis, pred_exist);
    hungarian_kernel<<<BB, 32>>>();
    pair_kernel<<<BB * GG, PP>>>(pred_pts, gt_points, gt_vis, pred_type, gt_type);
    final_kernel<<<1, 256>>>(pred_exist, out);
}

// round 2
// speedup vs baseline: 1.2059x; 1.2059x over previous
#include <cuda_runtime.h>
#include <cuda_bf16.h>
#include <math.h>

#define BB 16
#define QQ 50
#define GG 16
#define PP 64
#define NT 7
#define NSEG (PP - 1)

// Scratch (device globals; no allocation allowed)
__device__ float g_curve[BB * QQ * GG];
__device__ float g_dir[BB * QQ * GG];
__device__ float g_cost[BB * QQ * GG];
__device__ float g_blk_pair[BB];   // per-batch weighted pair-loss sum
__device__ float g_blk_x[BB];      // per-batch sum of matched pred_exist logits
__device__ int   g_done_counter;   // zero-init; last block resets to 0 each run

// ---------------------------------------------------------------------------
// Kernel A: cost matrix. One block per (b,q,g), 64 threads (one per point).
// Expanded point-seg distance:
//   d^2 = |p|^2 + [ pa - 2 t dot + t^2 |ab|^2 ],  pa = -2 p.a + |a|^2,
//   dot = p.ab - a.ab,  t = sat(dot * id)
// |p|^2 is constant across segments -> hoisted outside the min.
// Per-segment packed: A=(abx,aby,-a.ab,id)  B=(-2ax,-2ay,|a|^2,|ab|^2)
// ---------------------------------------------------------------------------
__global__ __launch_bounds__(PP) void cost_kernel(
    const float* __restrict__ pred_pts,
    const float* __restrict__ gt_pts,
    const float* __restrict__ gt_vis,
    const float* __restrict__ pred_exist)
{
    int blk = blockIdx.x;
    int g = blk % GG;
    int q = (blk / GG) % QQ;
    int b = blk / (GG * QQ);
    int t = threadIdx.x;   // 0..63
    int lane = t & 31, wid = t >> 5;

    __shared__ float2 sP[PP], sG[PP];
    __shared__ float  sV[PP];
    __shared__ float4 sAg[NSEG], sBg[NSEG];   // gt segments
    __shared__ float4 sAp[NSEG], sBp[NSEG];   // pred segments
    __shared__ float2 sTg[NSEG], sTp[NSEG];   // unit tangents
    __shared__ float  sred[5][2];

    const float2* pp = (const float2*)(pred_pts + ((size_t)(b * QQ + q)) * PP * 2);
    const float2* gp = (const float2*)(gt_pts   + ((size_t)(b * GG + g)) * PP * 2);
    float2 myP = pp[t];
    float2 myG = gp[t];
    sP[t] = myP;
    sG[t] = myG;
    float myV = gt_vis[(size_t)(b * GG + g) * PP + t];
    sV[t] = myV;
    __syncthreads();

    if (t < NSEG) {
        // pred side
        {
            float2 a = sP[t], bp = sP[t + 1];
            float abx = bp.x - a.x, aby = bp.y - a.y;
            float ab2 = abx * abx + aby * aby;
            float id = 1.0f / fmaxf(ab2, 1e-8f);
            sAp[t] = make_float4(abx, aby, -(a.x * abx + a.y * aby), id);
            sBp[t] = make_float4(-2.0f * a.x, -2.0f * a.y, a.x * a.x + a.y * a.y, ab2);
            float n = fmaxf(sqrtf(ab2), 1e-6f);
            sTp[t] = make_float2(abx / n, aby / n);
        }
        // gt side
        {
            float2 a = sG[t], bp = sG[t + 1];
            float abx = bp.x - a.x, aby = bp.y - a.y;
            float ab2 = abx * abx + aby * aby;
            float id = 1.0f / fmaxf(ab2, 1e-8f);
            sAg[t] = make_float4(abx, aby, -(a.x * abx + a.y * aby), id);
            sBg[t] = make_float4(-2.0f * a.x, -2.0f * a.y, a.x * a.x + a.y * a.y, ab2);
            float n = fmaxf(sqrtf(ab2), 1e-6f);
            sTg[t] = make_float2(abx / n, aby / n);
        }
    }
    __syncthreads();

    float p2p = myP.x * myP.x + myP.y * myP.y;   // |pred point|^2
    float p2g = myG.x * myG.x + myG.y * myG.y;   // |gt point|^2
    float m1 = 3.0e38f, m2 = 3.0e38f;

    #pragma unroll 4
    for (int j = 0; j < NSEG; j++) {
        // pred point t vs gt segment j
        {
            float4 A = sAg[j], Bv = sBg[j];
            float dot = fmaf(myP.x, A.x, fmaf(myP.y, A.y, A.z));
            float pa  = fmaf(myP.x, Bv.x, fmaf(myP.y, Bv.y, Bv.z));
            float tt  = __saturatef(dot * A.w);
            float w   = fmaf(tt, Bv.w, -2.0f * dot);
            m1 = fminf(m1, fmaf(tt, w, pa));
        }
        // gt point t vs pred segment j
        {
            float4 A = sAp[j], Bv = sBp[j];
            float dot = fmaf(myG.x, A.x, fmaf(myG.y, A.y, A.z));
            float pa  = fmaf(myG.x, Bv.x, fmaf(myG.y, Bv.y, Bv.z));
            float tt  = __saturatef(dot * A.w);
            float w   = fmaf(tt, Bv.w, -2.0f * dot);
            m2 = fminf(m2, fmaf(tt, w, pa));
        }
    }
    float v0 = sqrtf(fmaxf(m1 + p2p, 1e-24f));          // dp2g
    float v1 = sqrtf(fmaxf(m2 + p2g, 1e-24f)) * myV;    // dg2p * vis
    float v2 = myV;
    float v3 = 0.0f, v4 = 0.0f;
    if (t < NSEG) {
        float sv = myV * sV[t + 1];
        float dot = sTp[t].x * sTg[t].x + sTp[t].y * sTg[t].y;
        v3 = (1.0f - dot) * sv;
        v4 = sv;
    }

    #pragma unroll
    for (int off = 16; off > 0; off >>= 1) {
        v0 += __shfl_down_sync(0xffffffffu, v0, off);
        v1 += __shfl_down_sync(0xffffffffu, v1, off);
        v2 += __shfl_down_sync(0xffffffffu, v2, off);
        v3 += __shfl_down_sync(0xffffffffu, v3, off);
        v4 += __shfl_down_sync(0xffffffffu, v4, off);
    }
    if (lane == 0) {
        sred[0][wid] = v0; sred[1][wid] = v1; sred[2][wid] = v2;
        sred[3][wid] = v3; sred[4][wid] = v4;
    }
    __syncthreads();
    if (t == 0) {
        float s0 = sred[0][0] + sred[0][1];
        float s1 = sred[1][0] + sred[1][1];
        float s2 = sred[2][0] + sred[2][1];
        float s3 = sred[3][0] + sred[3][1];
        float s4 = sred[4][0] + sred[4][1];
        float visS = fmaxf(s2, 1.0f);
        float curve = 0.5f * (s0 * (1.0f / PP) + s1 / visS);
        float dir = s3 / fmaxf(s4, 1.0f);
        int idx = (b * QQ + q) * GG + g;
        g_curve[idx] = curve;
        g_dir[idx] = dir;
        float x = pred_exist[b * QQ + q];
        float sig = 1.0f / (1.0f + expf(-x));
        g_cost[idx] = curve + 0.35f * dir - 0.25f * sig;
    }
}

// ---------------------------------------------------------------------------
// Kernel B: per-batch JV Hungarian (warp 0) + matched-pair losses (4 warps)
// + last-block-done final reduction (BCE + totals) -> out[0].
// Rows = 16 gt lanes, cols = 50 preds (equivalent to reference's padded
// square: pad columns have constant cost).
// ---------------------------------------------------------------------------
__device__ __forceinline__ unsigned okey(float f) {
    unsigned u = __float_as_uint(f);
    return (u & 0x80000000u) ? ~u : (u | 0x80000000u);
}
__device__ __forceinline__ float smooth_l1(float x) {
    float ax = fabsf(x);
    return (ax < 1.0f) ? 0.5f * x * x : ax - 0.5f;
}

__global__ __launch_bounds__(128) void hungarian_pair_final_kernel(
    const float* __restrict__ pred_exist,
    const float* __restrict__ pred_pts,
    const float* __restrict__ pred_type,
    const float* __restrict__ gt_pts,
    const float* __restrict__ gt_vis,
    const int*   __restrict__ gt_type,
    float* __restrict__ out)
{
    int b = blockIdx.x;
    int tid = threadIdx.x;
    int lane = tid & 31, warp = tid >> 5;

    __shared__ float sC[GG][QQ];
    __shared__ float su[GG + 1];
    __shared__ int   sp[QQ + 1];
    __shared__ int   sway[QQ + 1];
    __shared__ int   s_match[GG];
    __shared__ float s_wsum[4];
    __shared__ float s_xsum;
    __shared__ int   s_last;
    __shared__ float s_red[128];

    // load costs (transposed): sC[g][q]
    for (int idx = tid; idx < GG * QQ; idx += 128) {
        int qq = idx >> 4, gg = idx & 15;
        sC[gg][qq] = g_cost[(b * QQ + qq) * GG + gg];
    }
    if (tid <= QQ) sp[tid] = 0;
    if (tid <= GG) su[tid] = 0.0f;
    __syncthreads();

    // ---- Phase 1: JV on warp 0 ----
    if (warp == 0) {
        const float INF_F = 1e30f;
        float v0 = 0.0f, v1 = 0.0f;       // duals for cols lane, lane+32
        int c1 = lane + 32;
        bool have1 = (c1 < QQ);

        for (int i = 1; i <= GG; ++i) {
            if (lane == 0) sp[0] = i;
            float minv0 = INF_F, minv1 = INF_F;
            bool used0 = false, used1 = false;
            __syncwarp();
            int j0 = 0;
            while (true) {
                if (j0 > 0) {
                    int c = j0 - 1;
                    if ((c & 31) == lane) { if (c < 32) used0 = true; else used1 = true; }
                }
                int i0 = sp[j0];
                float ui0 = su[i0];
                // slot 0
                float cur0 = sC[i0 - 1][lane] - ui0 - v0;
                if (!used0 && cur0 < minv0) { minv0 = cur0; sway[lane + 1] = j0; }
                float cand0 = used0 ? INF_F : minv0;
                // slot 1
                float cand1 = INF_F;
                if (have1) {
                    float cur1 = sC[i0 - 1][c1] - ui0 - v1;
                    if (!used1 && cur1 < minv1) { minv1 = cur1; sway[c1 + 1] = j0; }
                    if (!used1) cand1 = minv1;
                }
                float bval = cand0; int bcol = lane;
                if (cand1 < bval) { bval = cand1; bcol = c1; }

                unsigned key = okey(bval);
                unsigned kmin = __reduce_min_sync(0xffffffffu, key);
                unsigned ball = __ballot_sync(0xffffffffu, key == kmin);
                int lead = __ffs(ball) - 1;
                int bj   = __shfl_sync(0xffffffffu, bcol, lead) + 1;
                float delta = __shfl_sync(0xffffffffu, bval, lead);

                if (used0) v0 -= delta; else minv0 -= delta;
                if (have1) { if (used1) v1 -= delta; else minv1 -= delta; }
                // dual u updates: distinct rows per used column -> race-free
                if (used0)          su[sp[lane + 1]] += delta;
                if (have1 && used1) su[sp[c1 + 1]]   += delta;
                if (lane == 0)      su[sp[0]]        += delta;
                __syncwarp();
                j0 = bj;
                if (sp[j0] == 0) break;
            }
            if (lane == 0) {
                int jj = j0;
                while (jj) { int jn = sway[jj]; sp[jj] = sp[jn]; jj = jn; }
            }
            __syncwarp();
        }
        // extract matches: sp[j] = row assigned to column j
        {
            int r = sp[lane + 1];
            if (r > 0) s_match[r - 1] = lane;
            if (have1) { int r2 = sp[c1 + 1]; if (r2 > 0) s_match[r2 - 1] = c1; }
        }
        __syncwarp();
        // matched-x sum for BCE decomposition
        float xs = (lane < GG) ? pred_exist[b * QQ + s_match[lane]] : 0.0f;
        #pragma unroll
        for (int off = 16; off > 0; off >>= 1) xs += __shfl_down_sync(0xffffffffu, xs, off);
        if (lane == 0) s_xsum = xs;
    }
    __syncthreads();

    // ---- Phase 2: pair losses; warp w handles g = 4w..4w+3 ----
    float acc = 0.0f;
    for (int k = 0; k < 4; k++) {
        int g = warp * 4 + k;
        int row = s_match[g];
        const float* pp = pred_pts + (size_t)(b * QQ + row) * PP * 2;
        const float* gp = gt_pts   + (size_t)(b * GG + g) * PP * 2;
        const float* vp = gt_vis   + (size_t)(b * GG + g) * PP;

        float ptsv = 0.0f, viss = 0.0f, smv = 0.0f, cvs = 0.0f;
        #pragma unroll
        for (int h = 0; h < 2; h++) {
            int t = lane + 32 * h;
            float px = pp[2 * t], py = pp[2 * t + 1];
            float gx = gp[2 * t], gy = gp[2 * t + 1];
            float v = vp[t];
            ptsv += (smooth_l1(px - gx) + smooth_l1(py - gy)) * v;
            viss += v;
            if (t >= 1 && t <= PP - 2) {
                float sx = pp[2 * t + 2] - 2.0f * px + pp[2 * t - 2];
                float sy = pp[2 * t + 3] - 2.0f * py + pp[2 * t - 1];
                float mag = sqrtf(fmaxf(sx * sx + sy * sy, 1e-24f));
                float cv = vp[t - 1] * v * vp[t + 1];
                smv += mag * cv;
                cvs += cv;
            }
        }
        #pragma unroll
        for (int off = 16; off > 0; off >>= 1) {
            ptsv += __shfl_down_sync(0xffffffffu, ptsv, off);
            viss += __shfl_down_sync(0xffffffffu, viss, off);
            smv  += __shfl_down_sync(0xffffffffu, smv, off);
            cvs  += __shfl_down_sync(0xffffffffu, cvs, off);
        }
        if (lane == 0) {
            float visS = fmaxf(viss, 1.0f);
            float pts = ptsv / visS;
            float smooth = smv / fmaxf(cvs, 1.0f);
            const float* lg = pred_type + (size_t)(b * QQ + row) * NT;
            int label = gt_type[b * GG + g];
            float mx = lg[0];
            #pragma unroll
            for (int n = 1; n < NT; n++) mx = fmaxf(mx, lg[n]);
            float se = 0.0f;
            #pragma unroll
            for (int n = 0; n < NT; n++) se += expf(lg[n] - mx);
            float ce = mx + logf(se) - lg[label];
            int ci = (b * QQ + row) * GG + g;
            acc += 3.0f * pts + 5.0f * g_curve[ci] + 1.5f * g_dir[ci] +
                   0.25f * smooth + 0.5f * ce;
        }
    }
    if (lane == 0) s_wsum[warp] = acc;
    __syncthreads();

    if (tid == 0) {
        g_blk_pair[b] = s_wsum[0] + s_wsum[1] + s_wsum[2] + s_wsum[3];
        g_blk_x[b] = s_xsum;
        __threadfence();
        int old = atomicAdd(&g_done_counter, 1);
        s_last = (old == BB - 1) ? 1 : 0;
    }
    __syncthreads();
    if (!s_last) return;

    // ---- Phase 3 (last block): BCE(base) + combine -> scalar ----
    float bacc = 0.0f;
    for (int i = tid; i < BB * QQ; i += 128) {
        float x = pred_exist[i];
        bacc += fmaxf(x, 0.0f) + log1pf(expf(-fabsf(x)));
    }
    float pacc = 0.0f, xacc = 0.0f;
    if (tid < BB) {
        pacc = *((volatile float*)&g_blk_pair[tid]);
        xacc = *((volatile float*)&g_blk_x[tid]);
    }
    s_red[tid] = bacc;
    __syncthreads();
    for (int s = 64; s > 0; s >>= 1) {
        if (tid < s) s_red[tid] += s_red[tid + s];
        __syncthreads();
    }
    float bce_sum = s_red[0];
    __syncthreads();
    s_red[tid] = pacc;
    __syncthreads();
    for (int s = 64; s > 0; s >>= 1) {
        if (tid < s) s_red[tid] += s_red[tid + s];
        __syncthreads();
    }
    float pair_sum = s_red[0];
    __syncthreads();
    s_red[tid] = xacc;
    __syncthreads();
    for (int s = 64; s > 0; s >>= 1) {
        if (tid < s) s_red[tid] += s_red[tid + s];
        __syncthreads();
    }
    if (tid == 0) {
        float x_sum = s_red[0];
        float bce = (bce_sum - x_sum) * (1.0f / (BB * QQ));
        out[0] = 1.5f * bce + pair_sum * (1.0f / (BB * GG));
        g_done_counter = 0;   // reset for next graph replay
    }
}

// ---------------------------------------------------------------------------
extern "C" void kernel_launch(void* const* d_in, const int* in_sizes, int n_in,
                              void* d_out, int out_size)
{
    const float* pred_exist = (const float*)d_in[0];
    const float* pred_pts   = (const float*)d_in[1];
    const float* pred_type  = (const float*)d_in[2];
    const float* gt_points  = (const float*)d_in[4];
    const float* gt_vis     = (const float*)d_in[5];
    const int*   gt_type    = (const int*)d_in[6];
    float* out = (float*)d_out;

    cost_kernel<<<BB * QQ * GG, PP>>>(pred_pts, gt_points, gt_vis, pred_exist);
    hungarian_pair_final_kernel<<<BB, 128>>>(pred_exist, pred_pts, pred_type,
                                             gt_points, gt_vis, gt_type, out);
}

// round 3
// speedup vs baseline: 1.5405x; 1.2774x over previous
#include <cuda_runtime.h>
#include <cuda_bf16.h>
#include <math.h>

#define BB 16
#define QQ 50
#define GG 16
#define PP 64
#define NT 7
#define NSEG (PP - 1)

typedef unsigned long long u64;

// packed f32x2 helpers
#define F2PACK(d, lo, hi)  asm("mov.b64 %0, {%1,%2};" : "=l"(d) : "f"(lo), "f"(hi))
#define F2UNPACK(lo, hi, s) asm("mov.b64 {%0,%1}, %2;" : "=f"(lo), "=f"(hi) : "l"(s))
#define F2FMA(d, a, b, c)  asm("fma.rn.f32x2 %0, %1, %2, %3;" : "=l"(d) : "l"(a), "l"(b), "l"(c))
#define F2MUL(d, a, b)     asm("mul.rn.f32x2 %0, %1, %2;" : "=l"(d) : "l"(a), "l"(b))

// Scratch (device globals; no allocation allowed)
__device__ float g_curve[BB * QQ * GG];
__device__ float g_dir[BB * QQ * GG];
__device__ float g_cost[BB * QQ * GG];
__device__ float g_blk_pair[BB];
__device__ float g_blk_x[BB];
__device__ float g_blk_bce[BB];
__device__ int   g_done_counter;   // zero-init; last block resets each run

// ---------------------------------------------------------------------------
// Kernel A: cost matrix. One block per (b,q,g), 64 threads (one per point).
// Both directions (p2g / g2p) packed into f32x2 lanes:
//   lo half: pred point vs gt segments,  hi half: gt point vs pred segments.
// Per segment j (per side): n = ab/max(|ab|^2,1e-8), cr = -(a.n)
//   r   = p.n + cr                    (unclamped param)
//   pa  = -2 a.p + |a|^2              (= |p-a|^2 - |p|^2)
//   t   = sat(r)
//   d^2 - |p|^2 = pa + ab2 * t * (t - 2r)
// min over j, then add |p|^2 and sqrt once.
// ---------------------------------------------------------------------------
__global__ __launch_bounds__(PP) void cost_kernel(
    const float* __restrict__ pred_pts,
    const float* __restrict__ gt_pts,
    const float* __restrict__ gt_vis,
    const float* __restrict__ pred_exist)
{
    int blk = blockIdx.x;
    int g = blk % GG;
    int q = (blk / GG) % QQ;
    int b = blk / (GG * QQ);
    int t = threadIdx.x;   // 0..63
    int lane = t & 31, wid = t >> 5;

    __shared__ float2 sP[PP], sG[PP];
    __shared__ float  sV[PP];
    // interleaved (gt, pred) segment params
    __shared__ float4 sA0[NSEG];   // (nx_g, nx_p, ny_g, ny_p)
    __shared__ float4 sA1[NSEG];   // (cr_g, cr_p, bx_g, bx_p)
    __shared__ float4 sB0[NSEG];   // (by_g, by_p, cpa_g, cpa_p)
    __shared__ float2 sB1[NSEG];   // (ab2_g, ab2_p)
    __shared__ float  sTdot[NSEG]; // unit tangent dot
    __shared__ float  sred[5][2];

    const float2* pp = (const float2*)(pred_pts + ((size_t)(b * QQ + q)) * PP * 2);
    const float2* gp = (const float2*)(gt_pts   + ((size_t)(b * GG + g)) * PP * 2);
    float2 myP = pp[t];
    float2 myG = gp[t];
    sP[t] = myP;
    sG[t] = myG;
    float myV = gt_vis[(size_t)(b * GG + g) * PP + t];
    sV[t] = myV;
    __syncthreads();

    if (t < NSEG) {
        // gt side
        float2 aG = sG[t], bG = sG[t + 1];
        float abxg = bG.x - aG.x, abyg = bG.y - aG.y;
        float ab2g = abxg * abxg + abyg * abyg;
        float invg = 1.0f / fmaxf(ab2g, 1e-8f);
        float nxg = abxg * invg, nyg = abyg * invg;
        float crg = -(aG.x * abxg + aG.y * abyg) * invg;
        // pred side
        float2 aP = sP[t], bP = sP[t + 1];
        float abxp = bP.x - aP.x, abyp = bP.y - aP.y;
        float ab2p = abxp * abxp + abyp * abyp;
        float invp = 1.0f / fmaxf(ab2p, 1e-8f);
        float nxp = abxp * invp, nyp = abyp * invp;
        float crp = -(aP.x * abxp + aP.y * abyp) * invp;

        sA0[t] = make_float4(nxg, nxp, nyg, nyp);
        sA1[t] = make_float4(crg, crp, -2.0f * aG.x, -2.0f * aP.x);
        sB0[t] = make_float4(-2.0f * aG.y, -2.0f * aP.y,
                             aG.x * aG.x + aG.y * aG.y,
                             aP.x * aP.x + aP.y * aP.y);
        sB1[t] = make_float2(ab2g, ab2p);

        float itg = 1.0f / fmaxf(sqrtf(ab2g), 1e-6f);
        float itp = 1.0f / fmaxf(sqrtf(ab2p), 1e-6f);
        sTdot[t] = (abxp * abxg + abyp * abyg) * itg * itp;
    }
    __syncthreads();

    // packed points: lo = pred point (vs gt segs), hi = gt point (vs pred segs)
    u64 Px2, Py2, NEG2;
    F2PACK(Px2, myP.x, myG.x);
    F2PACK(Py2, myP.y, myG.y);
    F2PACK(NEG2, -2.0f, -2.0f);

    float mLo = 3.0e38f, mHi = 3.0e38f;

    #pragma unroll 3
    for (int j = 0; j < NSEG; j++) {
        float4 A0 = sA0[j];
        float4 A1 = sA1[j];
        float4 B0 = sB0[j];
        float2 B1 = sB1[j];
        u64 nx2, ny2, cr2, bx2, by2, cpa2, ab22;
        F2PACK(nx2, A0.x, A0.y);  F2PACK(ny2, A0.z, A0.w);
        F2PACK(cr2, A1.x, A1.y);  F2PACK(bx2, A1.z, A1.w);
        F2PACK(by2, B0.x, B0.y);  F2PACK(cpa2, B0.z, B0.w);
        F2PACK(ab22, B1.x, B1.y);

        u64 r2, pa2, t2, w2, z2, val2;
        F2FMA(r2, Py2, ny2, cr2);
        F2FMA(r2, Px2, nx2, r2);
        F2FMA(pa2, Py2, by2, cpa2);
        F2FMA(pa2, Px2, bx2, pa2);
        float rl, rh;
        F2UNPACK(rl, rh, r2);
        float tl = __saturatef(rl), th = __saturatef(rh);
        F2PACK(t2, tl, th);
        F2FMA(w2, r2, NEG2, t2);     // t - 2r
        F2MUL(z2, t2, w2);
        F2FMA(val2, z2, ab22, pa2);
        float vl, vh;
        F2UNPACK(vl, vh, val2);
        mLo = fminf(mLo, vl);
        mHi = fminf(mHi, vh);
    }

    float pp2 = myP.x * myP.x + myP.y * myP.y;
    float gg2 = myG.x * myG.x + myG.y * myG.y;
    float v0 = sqrtf(fmaxf(mLo + pp2, 1e-24f));          // dp2g
    float v1 = sqrtf(fmaxf(mHi + gg2, 1e-24f)) * myV;    // dg2p * vis
    float v2 = myV;
    float v3 = 0.0f, v4 = 0.0f;
    if (t < NSEG) {
        float sv_ = myV * sV[t + 1];
        v3 = (1.0f - sTdot[t]) * sv_;
        v4 = sv_;
    }

    #pragma unroll
    for (int off = 16; off > 0; off >>= 1) {
        v0 += __shfl_down_sync(0xffffffffu, v0, off);
        v1 += __shfl_down_sync(0xffffffffu, v1, off);
        v2 += __shfl_down_sync(0xffffffffu, v2, off);
        v3 += __shfl_down_sync(0xffffffffu, v3, off);
        v4 += __shfl_down_sync(0xffffffffu, v4, off);
    }
    if (lane == 0) {
        sred[0][wid] = v0; sred[1][wid] = v1; sred[2][wid] = v2;
        sred[3][wid] = v3; sred[4][wid] = v4;
    }
    __syncthreads();
    if (t == 0) {
        float s0 = sred[0][0] + sred[0][1];
        float s1 = sred[1][0] + sred[1][1];
        float s2 = sred[2][0] + sred[2][1];
        float s3 = sred[3][0] + sred[3][1];
        float s4 = sred[4][0] + sred[4][1];
        float visS = fmaxf(s2, 1.0f);
        float curve = 0.5f * (s0 * (1.0f / PP) + s1 / visS);
        float dir = s3 / fmaxf(s4, 1.0f);
        int idx = (b * QQ + q) * GG + g;
        g_curve[idx] = curve;
        g_dir[idx] = dir;
        float x = pred_exist[b * QQ + q];
        float sig = 1.0f / (1.0f + expf(-x));
        g_cost[idx] = curve + 0.35f * dir - 0.25f * sig;
    }
}

// ---------------------------------------------------------------------------
// Kernel B: LAPJV Hungarian (warp 0, register-resident Dijkstra) + BCE-base
// prep (warp 1) + matched-pair losses (all warps) + last-block final combine.
// ---------------------------------------------------------------------------
__device__ __forceinline__ unsigned okey(float f) {
    unsigned u = __float_as_uint(f);
    return (u & 0x80000000u) ? ~u : (u | 0x80000000u);
}
__device__ __forceinline__ float smooth_l1(float x) {
    float ax = fabsf(x);
    return (ax < 1.0f) ? 0.5f * x * x : ax - 0.5f;
}

__global__ __launch_bounds__(128) void hungarian_pair_final_kernel(
    const float* __restrict__ pred_exist,
    const float* __restrict__ pred_pts,
    const float* __restrict__ pred_type,
    const float* __restrict__ gt_pts,
    const float* __restrict__ gt_vis,
    const int*   __restrict__ gt_type,
    float* __restrict__ out)
{
    int b = blockIdx.x;
    int tid = threadIdx.x;
    int lane = tid & 31, warp = tid >> 5;

    __shared__ float sC[GG][QQ];
    __shared__ float sv[QQ];
    __shared__ int   sRow[QQ];
    __shared__ int   sway[QQ];
    __shared__ int   s_match[GG];
    __shared__ float s_wsum[4];
    __shared__ float s_xsum, s_bce;
    __shared__ int   s_last;
    __shared__ float s_red[128];

    for (int idx = tid; idx < GG * QQ; idx += 128) {
        int qq = idx >> 4, gg = idx & 15;
        sC[gg][qq] = g_cost[(b * QQ + qq) * GG + gg];
    }
    if (tid < QQ) { sv[tid] = 0.0f; sRow[tid] = -1; }
    __syncthreads();

    if (warp == 0) {
        // ---- LAPJV: rows = 16 gt, cols = 50 preds ----
        const float INF_F = 1e30f;
        int c0 = lane, c1 = lane + 32;
        bool have1 = (c1 < QQ);
        float v0 = 0.0f, v1 = 0.0f;

        for (int r0 = 0; r0 < GG; ++r0) {
            float d0 = sC[r0][c0] - v0;
            float d1 = have1 ? (sC[r0][c1] - v1) : INF_F;
            sway[c0] = -1;
            if (have1) sway[c1] = -1;
            bool sc0 = false, sc1 = false;
            int jf; float D;

            while (true) {
                float cand0 = sc0 ? INF_F : d0;
                float cand1 = sc1 ? INF_F : d1;
                float bval = cand0; int bcol = c0;
                if (cand1 < bval) { bval = cand1; bcol = c1; }
                unsigned key = okey(bval);
                unsigned kmin = __reduce_min_sync(0xffffffffu, key);
                unsigned ball = __ballot_sync(0xffffffffu, key == kmin);
                int lead = __ffs(ball) - 1;
                int js = __shfl_sync(0xffffffffu, bcol, lead);
                D      = __shfl_sync(0xffffffffu, bval, lead);
                if (lane == (js & 31)) { if (js < 32) sc0 = true; else sc1 = true; }
                int r = sRow[js];
                if (r < 0) { jf = js; break; }
                // static-potential relax (v fixed during Dijkstra)
                float h = sC[r][js] - sv[js] - D;
                float a0 = sC[r][c0] - v0 - h;
                if (!sc0 && a0 < d0) { d0 = a0; sway[c0] = js; }
                if (have1) {
                    float a1 = sC[r][c1] - v1 - h;
                    if (!sc1 && a1 < d1) { d1 = a1; sway[c1] = js; }
                }
            }
            // potential update for scanned columns
            if (sc0) { v0 += d0 - D; sv[c0] = v0; }
            if (sc1) { v1 += d1 - D; sv[c1] = v1; }
            __syncwarp();
            if (lane == 0) {
                int cur = jf;
                while (true) {
                    int src = sway[cur];
                    if (src < 0) { sRow[cur] = r0; break; }
                    sRow[cur] = sRow[src];
                    cur = src;
                }
            }
            __syncwarp();
        }
        // extract matches
        {
            int r = sRow[c0];
            if (r >= 0) s_match[r] = c0;
            if (have1) { int r2 = sRow[c1]; if (r2 >= 0) s_match[r2] = c1; }
        }
        __syncwarp();
        float xs = (lane < GG) ? pred_exist[b * QQ + s_match[lane]] : 0.0f;
        #pragma unroll
        for (int off = 16; off > 0; off >>= 1) xs += __shfl_down_sync(0xffffffffu, xs, off);
        if (lane == 0) s_xsum = xs;
    } else if (warp == 1) {
        // BCE base partial for this batch (independent of matching)
        float acc = 0.0f;
        for (int q_ = lane; q_ < QQ; q_ += 32) {
            float x = pred_exist[b * QQ + q_];
            acc += fmaxf(x, 0.0f) + log1pf(expf(-fabsf(x)));
        }
        #pragma unroll
        for (int off = 16; off > 0; off >>= 1) acc += __shfl_down_sync(0xffffffffu, acc, off);
        if (lane == 0) s_bce = acc;
    }
    __syncthreads();

    // ---- Phase 2: pair losses; warp w handles g = 4w..4w+3 ----
    float acc = 0.0f;
    for (int k = 0; k < 4; k++) {
        int g = warp * 4 + k;
        int row = s_match[g];
        const float* pp = pred_pts + (size_t)(b * QQ + row) * PP * 2;
        const float* gp = gt_pts   + (size_t)(b * GG + g) * PP * 2;
        const float* vp = gt_vis   + (size_t)(b * GG + g) * PP;

        float ptsv = 0.0f, viss = 0.0f, smv = 0.0f, cvs = 0.0f;
        #pragma unroll
        for (int h = 0; h < 2; h++) {
            int t = lane + 32 * h;
            float px = pp[2 * t], py = pp[2 * t + 1];
            float gx = gp[2 * t], gy = gp[2 * t + 1];
            float v = vp[t];
            ptsv += (smooth_l1(px - gx) + smooth_l1(py - gy)) * v;
            viss += v;
            if (t >= 1 && t <= PP - 2) {
                float sx = pp[2 * t + 2] - 2.0f * px + pp[2 * t - 2];
                float sy = pp[2 * t + 3] - 2.0f * py + pp[2 * t - 1];
                float mag = sqrtf(fmaxf(sx * sx + sy * sy, 1e-24f));
                float cv = vp[t - 1] * v * vp[t + 1];
                smv += mag * cv;
                cvs += cv;
            }
        }
        #pragma unroll
        for (int off = 16; off > 0; off >>= 1) {
            ptsv += __shfl_down_sync(0xffffffffu, ptsv, off);
            viss += __shfl_down_sync(0xffffffffu, viss, off);
            smv  += __shfl_down_sync(0xffffffffu, smv, off);
            cvs  += __shfl_down_sync(0xffffffffu, cvs, off);
        }
        if (lane == 0) {
            float visS = fmaxf(viss, 1.0f);
            float pts = ptsv / visS;
            float smooth = smv / fmaxf(cvs, 1.0f);
            const float* lg = pred_type + (size_t)(b * QQ + row) * NT;
            int label = gt_type[b * GG + g];
            float mx = lg[0];
            #pragma unroll
            for (int n = 1; n < NT; n++) mx = fmaxf(mx, lg[n]);
            float se = 0.0f;
            #pragma unroll
            for (int n = 0; n < NT; n++) se += expf(lg[n] - mx);
            float ce = mx + logf(se) - lg[label];
            int ci = (b * QQ + row) * GG + g;
            acc += 3.0f * pts + 5.0f * g_curve[ci] + 1.5f * g_dir[ci] +
                   0.25f * smooth + 0.5f * ce;
        }
    }
    if (lane == 0) s_wsum[warp] = acc;
    __syncthreads();

    if (tid == 0) {
        g_blk_pair[b] = s_wsum[0] + s_wsum[1] + s_wsum[2] + s_wsum[3];
        g_blk_x[b] = s_xsum;
        g_blk_bce[b] = s_bce;
        __threadfence();
        int old = atomicAdd(&g_done_counter, 1);
        s_last = (old == BB - 1) ? 1 : 0;
    }
    __syncthreads();
    if (!s_last) return;

    // ---- Phase 3 (last block): combine -> scalar ----
    float pacc = 0.0f, xacc = 0.0f, bacc = 0.0f;
    if (tid < BB) {
        pacc = *((volatile float*)&g_blk_pair[tid]);
        xacc = *((volatile float*)&g_blk_x[tid]);
        bacc = *((volatile float*)&g_blk_bce[tid]);
    }
    s_red[tid] = pacc;
    __syncthreads();
    for (int s = 64; s > 0; s >>= 1) { if (tid < s) s_red[tid] += s_red[tid + s]; __syncthreads(); }
    float pair_sum = s_red[0];
    __syncthreads();
    s_red[tid] = xacc;
    __syncthreads();
    for (int s = 64; s > 0; s >>= 1) { if (tid < s) s_red[tid] += s_red[tid + s]; __syncthreads(); }
    float x_sum = s_red[0];
    __syncthreads();
    s_red[tid] = bacc;
    __syncthreads();
    for (int s = 64; s > 0; s >>= 1) { if (tid < s) s_red[tid] += s_red[tid + s]; __syncthreads(); }
    if (tid == 0) {
        float bce_sum = s_red[0];
        float bce = (bce_sum - x_sum) * (1.0f / (BB * QQ));
        out[0] = 1.5f * bce + pair_sum * (1.0f / (BB * GG));
        g_done_counter = 0;
    }
}

// ---------------------------------------------------------------------------
extern "C" void kernel_launch(void* const* d_in, const int* in_sizes, int n_in,
                              void* d_out, int out_size)
{
    const float* pred_exist = (const float*)d_in[0];
    const float* pred_pts   = (const float*)d_in[1];
    const float* pred_type  = (const float*)d_in[2];
    const float* gt_points  = (const float*)d_in[4];
    const float* gt_vis     = (const float*)d_in[5];
    const int*   gt_type    = (const int*)d_in[6];
    float* out = (float*)d_out;

    cost_kernel<<<BB * QQ * GG, PP>>>(pred_pts, gt_points, gt_vis, pred_exist);
    hungarian_pair_final_kernel<<<BB, 128>>>(pred_exist, pred_pts, pred_type,
                                             gt_points, gt_vis, gt_type, out);
}

// round 4
// speedup vs baseline: 1.5461x; 1.0036x over previous
#include <cuda_runtime.h>
#include <cuda_bf16.h>
#include <math.h>

#define BB 16
#define QQ 50
#define GG 16
#define PP 64
#define NT 7
#define NSEG (PP - 1)

typedef unsigned long long u64;

// packed f32x2 helpers
#define F2PACK(d, lo, hi)  asm("mov.b64 %0, {%1,%2};" : "=l"(d) : "f"(lo), "f"(hi))
#define F2UNPACK(lo, hi, s) asm("mov.b64 {%0,%1}, %2;" : "=f"(lo), "=f"(hi) : "l"(s))
#define F2FMA(d, a, b, c)  asm("fma.rn.f32x2 %0, %1, %2, %3;" : "=l"(d) : "l"(a), "l"(b), "l"(c))
#define F2MUL(d, a, b)     asm("mul.rn.f32x2 %0, %1, %2;" : "=l"(d) : "l"(a), "l"(b))

// Scratch (device globals; no allocation allowed)
__device__ float g_curve[BB * QQ * GG];
__device__ float g_dir[BB * QQ * GG];
__device__ float g_cost[BB * QQ * GG];
__device__ float g_blk_pair[BB];
__device__ float g_blk_x[BB];
__device__ float g_blk_bce[BB];
__device__ int   g_done_counter;   // zero-init; last block resets each run

// ---------------------------------------------------------------------------
// Kernel A: cost matrix. One block per (b,q,g), 64 threads (one per point).
// p2g / g2p packed into f32x2 lanes (lo: pred pt vs gt segs, hi: gt pt vs
// pred segs).  d^2 - |p|^2 = pa + ab2 * t * (t - 2r),  t = clamp01(r).
// Clamps + mins on ALU pipe (FMNMX), 7 packed FFMA2/FMUL2 on fma pipe.
// ---------------------------------------------------------------------------
__global__ __launch_bounds__(PP) void cost_kernel(
    const float* __restrict__ pred_pts,
    const float* __restrict__ gt_pts,
    const float* __restrict__ gt_vis,
    const float* __restrict__ pred_exist)
{
    int blk = blockIdx.x;
    int g = blk % GG;
    int q = (blk / GG) % QQ;
    int b = blk / (GG * QQ);
    int t = threadIdx.x;   // 0..63
    int lane = t & 31, wid = t >> 5;

    __shared__ float2 sP[PP], sG[PP];
    __shared__ float  sV[PP];
    __shared__ float4 sA0[NSEG];   // (nx_g, nx_p, ny_g, ny_p)
    __shared__ float4 sA1[NSEG];   // (cr_g, cr_p, bx_g, bx_p)
    __shared__ float4 sB0[NSEG];   // (by_g, by_p, cpa_g, cpa_p)
    __shared__ float2 sB1[NSEG];   // (ab2_g, ab2_p)
    __shared__ float  sTdot[NSEG];
    __shared__ float  sred[5][2];

    const float2* pp = (const float2*)(pred_pts + ((size_t)(b * QQ + q)) * PP * 2);
    const float2* gp = (const float2*)(gt_pts   + ((size_t)(b * GG + g)) * PP * 2);
    float2 myP = pp[t];
    float2 myG = gp[t];
    sP[t] = myP;
    sG[t] = myG;
    float myV = gt_vis[(size_t)(b * GG + g) * PP + t];
    sV[t] = myV;
    __syncthreads();

    if (t < NSEG) {
        float2 aG = sG[t], bG = sG[t + 1];
        float abxg = bG.x - aG.x, abyg = bG.y - aG.y;
        float ab2g = abxg * abxg + abyg * abyg;
        float invg = 1.0f / fmaxf(ab2g, 1e-8f);
        float nxg = abxg * invg, nyg = abyg * invg;
        float crg = -(aG.x * abxg + aG.y * abyg) * invg;

        float2 aP = sP[t], bP = sP[t + 1];
        float abxp = bP.x - aP.x, abyp = bP.y - aP.y;
        float ab2p = abxp * abxp + abyp * abyp;
        float invp = 1.0f / fmaxf(ab2p, 1e-8f);
        float nxp = abxp * invp, nyp = abyp * invp;
        float crp = -(aP.x * abxp + aP.y * abyp) * invp;

        sA0[t] = make_float4(nxg, nxp, nyg, nyp);
        sA1[t] = make_float4(crg, crp, -2.0f * aG.x, -2.0f * aP.x);
        sB0[t] = make_float4(-2.0f * aG.y, -2.0f * aP.y,
                             aG.x * aG.x + aG.y * aG.y,
                             aP.x * aP.x + aP.y * aP.y);
        sB1[t] = make_float2(ab2g, ab2p);

        float itg = 1.0f / fmaxf(sqrtf(ab2g), 1e-6f);
        float itp = 1.0f / fmaxf(sqrtf(ab2p), 1e-6f);
        sTdot[t] = (abxp * abxg + abyp * abyg) * itg * itp;
    }
    __syncthreads();

    u64 Px2, Py2, NEG2;
    F2PACK(Px2, myP.x, myG.x);
    F2PACK(Py2, myP.y, myG.y);
    F2PACK(NEG2, -2.0f, -2.0f);

    float mLo = 3.0e38f, mHi = 3.0e38f;

    #pragma unroll 3
    for (int j = 0; j < NSEG; j++) {
        float4 A0 = sA0[j];
        float4 A1 = sA1[j];
        float4 B0 = sB0[j];
        float2 B1 = sB1[j];
        u64 nx2, ny2, cr2, bx2, by2, cpa2, ab22;
        F2PACK(nx2, A0.x, A0.y);  F2PACK(ny2, A0.z, A0.w);
        F2PACK(cr2, A1.x, A1.y);  F2PACK(bx2, A1.z, A1.w);
        F2PACK(by2, B0.x, B0.y);  F2PACK(cpa2, B0.z, B0.w);
        F2PACK(ab22, B1.x, B1.y);

        u64 r2, pa2, t2, w2, z2, val2;
        F2FMA(r2, Py2, ny2, cr2);
        F2FMA(r2, Px2, nx2, r2);
        F2FMA(pa2, Py2, by2, cpa2);
        F2FMA(pa2, Px2, bx2, pa2);
        float rl, rh;
        F2UNPACK(rl, rh, r2);
        // clamp01 via FMNMX (alu pipe) to keep fma pipe free
        float tl = fminf(fmaxf(rl, 0.0f), 1.0f);
        float th = fminf(fmaxf(rh, 0.0f), 1.0f);
        F2PACK(t2, tl, th);
        F2FMA(w2, r2, NEG2, t2);     // t - 2r
        F2MUL(z2, t2, w2);
        F2FMA(val2, z2, ab22, pa2);
        float vl, vh;
        F2UNPACK(vl, vh, val2);
        mLo = fminf(mLo, vl);
        mHi = fminf(mHi, vh);
    }

    float pp2 = myP.x * myP.x + myP.y * myP.y;
    float gg2 = myG.x * myG.x + myG.y * myG.y;
    float v0 = sqrtf(fmaxf(mLo + pp2, 1e-24f));          // dp2g
    float v1 = sqrtf(fmaxf(mHi + gg2, 1e-24f)) * myV;    // dg2p * vis
    float v2 = myV;
    float v3 = 0.0f, v4 = 0.0f;
    if (t < NSEG) {
        float sv_ = myV * sV[t + 1];
        v3 = (1.0f - sTdot[t]) * sv_;
        v4 = sv_;
    }

    #pragma unroll
    for (int off = 16; off > 0; off >>= 1) {
        v0 += __shfl_down_sync(0xffffffffu, v0, off);
        v1 += __shfl_down_sync(0xffffffffu, v1, off);
        v2 += __shfl_down_sync(0xffffffffu, v2, off);
        v3 += __shfl_down_sync(0xffffffffu, v3, off);
        v4 += __shfl_down_sync(0xffffffffu, v4, off);
    }
    if (lane == 0) {
        sred[0][wid] = v0; sred[1][wid] = v1; sred[2][wid] = v2;
        sred[3][wid] = v3; sred[4][wid] = v4;
    }
    __syncthreads();
    if (t == 0) {
        float s0 = sred[0][0] + sred[0][1];
        float s1 = sred[1][0] + sred[1][1];
        float s2 = sred[2][0] + sred[2][1];
        float s3 = sred[3][0] + sred[3][1];
        float s4 = sred[4][0] + sred[4][1];
        float visS = fmaxf(s2, 1.0f);
        float curve = 0.5f * (s0 * (1.0f / PP) + s1 / visS);
        float dir = s3 / fmaxf(s4, 1.0f);
        int idx = (b * QQ + q) * GG + g;
        g_curve[idx] = curve;
        g_dir[idx] = dir;
        float x = pred_exist[b * QQ + q];
        float sig = 1.0f / (1.0f + expf(-x));
        g_cost[idx] = curve + 0.35f * dir - 0.25f * sig;
    }
}

// ---------------------------------------------------------------------------
// Kernel B: LAPJV Hungarian (warp 0) with index-embedded REDUX argmin and
// register-resident potentials (duals broadcast by SHFL, no shared sv) +
// BCE-base (warp 1) + pair losses (all warps) + last-block final combine.
// ---------------------------------------------------------------------------
__device__ __forceinline__ unsigned okey(float f) {
    unsigned u = __float_as_uint(f);
    return (u & 0x80000000u) ? ~u : (u | 0x80000000u);
}
__device__ __forceinline__ float smooth_l1(float x) {
    float ax = fabsf(x);
    return (ax < 1.0f) ? 0.5f * x * x : ax - 0.5f;
}

__global__ __launch_bounds__(128) void hungarian_pair_final_kernel(
    const float* __restrict__ pred_exist,
    const float* __restrict__ pred_pts,
    const float* __restrict__ pred_type,
    const float* __restrict__ gt_pts,
    const float* __restrict__ gt_vis,
    const int*   __restrict__ gt_type,
    float* __restrict__ out)
{
    int b = blockIdx.x;
    int tid = threadIdx.x;
    int lane = tid & 31, warp = tid >> 5;

    __shared__ float sC[GG][QQ];
    __shared__ int   sRow[QQ];
    __shared__ int   sway[QQ];
    __shared__ int   s_match[GG];
    __shared__ float s_wsum[4];
    __shared__ float s_xsum, s_bce;
    __shared__ int   s_last;
    __shared__ float s_red[128];

    for (int idx = tid; idx < GG * QQ; idx += 128) {
        int qq = idx >> 4, gg = idx & 15;
        sC[gg][qq] = g_cost[(b * QQ + qq) * GG + gg];
    }
    if (tid < QQ) sRow[tid] = -1;
    __syncthreads();

    if (warp == 0) {
        // ---- LAPJV: rows = 16 gt, cols = 50 preds ----
        const float INF_F = 1e30f;
        int c0 = lane, c1 = lane + 32;
        bool have1 = (c1 < QQ);
        float v0 = 0.0f, v1 = 0.0f;  // register-resident column potentials

        for (int r0 = 0; r0 < GG; ++r0) {
            float d0 = sC[r0][c0] - v0;
            float d1 = have1 ? (sC[r0][c1] - v1) : INF_F;
            sway[c0] = -1;
            if (have1) sway[c1] = -1;
            bool sc0 = false, sc1 = false;
            int jf; float D;

            while (true) {
                float cand0 = sc0 ? INF_F : d0;
                float cand1 = sc1 ? INF_F : d1;
                float bval = cand0; int bcol = c0;
                if (cand1 < bval) { bval = cand1; bcol = c1; }
                // index embedded in low 6 bits: one REDUX gives the winner col
                unsigned key = (okey(bval) & 0xFFFFFFC0u) | (unsigned)bcol;
                unsigned kmin = __reduce_min_sync(0xffffffffu, key);
                int js = (int)(kmin & 63u);
                int jl = js & 31;
                bool hiSlot = (js >= 32);
                // exact D and v[js] from owner lane (independent shuffles)
                float sendD = hiSlot ? d1 : d0;
                float sendV = hiSlot ? v1 : v0;
                D         = __shfl_sync(0xffffffffu, sendD, jl);
                float Vjs = __shfl_sync(0xffffffffu, sendV, jl);
                if (lane == jl) { if (hiSlot) sc1 = true; else sc0 = true; }
                int r = sRow[js];
                if (r < 0) { jf = js; break; }
                float h = sC[r][js] - Vjs - D;
                float a0 = sC[r][c0] - v0 - h;
                if (!sc0 && a0 < d0) { d0 = a0; sway[c0] = js; }
                if (have1) {
                    float a1 = sC[r][c1] - v1 - h;
                    if (!sc1 && a1 < d1) { d1 = a1; sway[c1] = js; }
                }
            }
            // potential update for scanned columns
            if (sc0) v0 += d0 - D;
            if (sc1) v1 += d1 - D;
            __syncwarp();
            if (lane == 0) {
                int cur = jf;
                while (true) {
                    int src = sway[cur];
                    if (src < 0) { sRow[cur] = r0; break; }
                    sRow[cur] = sRow[src];
                    cur = src;
                }
            }
            __syncwarp();
        }
        // extract matches
        {
            int r = sRow[c0];
            if (r >= 0) s_match[r] = c0;
            if (have1) { int r2 = sRow[c1]; if (r2 >= 0) s_match[r2] = c1; }
        }
        __syncwarp();
        float xs = (lane < GG) ? pred_exist[b * QQ + s_match[lane]] : 0.0f;
        #pragma unroll
        for (int off = 16; off > 0; off >>= 1) xs += __shfl_down_sync(0xffffffffu, xs, off);
        if (lane == 0) s_xsum = xs;
    } else if (warp == 1) {
        float acc = 0.0f;
        for (int q_ = lane; q_ < QQ; q_ += 32) {
            float x = pred_exist[b * QQ + q_];
            acc += fmaxf(x, 0.0f) + log1pf(expf(-fabsf(x)));
        }
        #pragma unroll
        for (int off = 16; off > 0; off >>= 1) acc += __shfl_down_sync(0xffffffffu, acc, off);
        if (lane == 0) s_bce = acc;
    }
    __syncthreads();

    // ---- Phase 2: pair losses; warp w handles g = 4w..4w+3 ----
    float acc = 0.0f;
    for (int k = 0; k < 4; k++) {
        int g = warp * 4 + k;
        int row = s_match[g];
        const float* pp = pred_pts + (size_t)(b * QQ + row) * PP * 2;
        const float* gp = gt_pts   + (size_t)(b * GG + g) * PP * 2;
        const float* vp = gt_vis   + (size_t)(b * GG + g) * PP;

        float ptsv = 0.0f, viss = 0.0f, smv = 0.0f, cvs = 0.0f;
        #pragma unroll
        for (int h = 0; h < 2; h++) {
            int t = lane + 32 * h;
            float px = pp[2 * t], py = pp[2 * t + 1];
            float gx = gp[2 * t], gy = gp[2 * t + 1];
            float v = vp[t];
            ptsv += (smooth_l1(px - gx) + smooth_l1(py - gy)) * v;
            viss += v;
            if (t >= 1 && t <= PP - 2) {
                float sx = pp[2 * t + 2] - 2.0f * px + pp[2 * t - 2];
                float sy = pp[2 * t + 3] - 2.0f * py + pp[2 * t - 1];
                float mag = sqrtf(fmaxf(sx * sx + sy * sy, 1e-24f));
                float cv = vp[t - 1] * v * vp[t + 1];
                smv += mag * cv;
                cvs += cv;
            }
        }
        #pragma unroll
        for (int off = 16; off > 0; off >>= 1) {
            ptsv += __shfl_down_sync(0xffffffffu, ptsv, off);
            viss += __shfl_down_sync(0xffffffffu, viss, off);
            smv  += __shfl_down_sync(0xffffffffu, smv, off);
            cvs  += __shfl_down_sync(0xffffffffu, cvs, off);
        }
        if (lane == 0) {
            float visS = fmaxf(viss, 1.0f);
            float pts = ptsv / visS;
            float smooth = smv / fmaxf(cvs, 1.0f);
            const float* lg = pred_type + (size_t)(b * QQ + row) * NT;
            int label = gt_type[b * GG + g];
            float mx = lg[0];
            #pragma unroll
            for (int n = 1; n < NT; n++) mx = fmaxf(mx, lg[n]);
            float se = 0.0f;
            #pragma unroll
            for (int n = 0; n < NT; n++) se += expf(lg[n] - mx);
            float ce = mx + logf(se) - lg[label];
            int ci = (b * QQ + row) * GG + g;
            acc += 3.0f * pts + 5.0f * g_curve[ci] + 1.5f * g_dir[ci] +
                   0.25f * smooth + 0.5f * ce;
        }
    }
    if (lane == 0) s_wsum[warp] = acc;
    __syncthreads();

    if (tid == 0) {
        g_blk_pair[b] = s_wsum[0] + s_wsum[1] + s_wsum[2] + s_wsum[3];
        g_blk_x[b] = s_xsum;
        g_blk_bce[b] = s_bce;
        __threadfence();
        int old = atomicAdd(&g_done_counter, 1);
        s_last = (old == BB - 1) ? 1 : 0;
    }
    __syncthreads();
    if (!s_last) return;

    // ---- Phase 3 (last block): combine -> scalar ----
    float pacc = 0.0f, xacc = 0.0f, bacc = 0.0f;
    if (tid < BB) {
        pacc = *((volatile float*)&g_blk_pair[tid]);
        xacc = *((volatile float*)&g_blk_x[tid]);
        bacc = *((volatile float*)&g_blk_bce[tid]);
    }
    s_red[tid] = pacc;
    __syncthreads();
    for (int s = 64; s > 0; s >>= 1) { if (tid < s) s_red[tid] += s_red[tid + s]; __syncthreads(); }
    float pair_sum = s_red[0];
    __syncthreads();
    s_red[tid] = xacc;
    __syncthreads();
    for (int s = 64; s > 0; s >>= 1) { if (tid < s) s_red[tid] += s_red[tid + s]; __syncthreads(); }
    float x_sum = s_red[0];
    __syncthreads();
    s_red[tid] = bacc;
    __syncthreads();
    for (int s = 64; s > 0; s >>= 1) { if (tid < s) s_red[tid] += s_red[tid + s]; __syncthreads(); }
    if (tid == 0) {
        float bce_sum = s_red[0];
        float bce = (bce_sum - x_sum) * (1.0f / (BB * QQ));
        out[0] = 1.5f * bce + pair_sum * (1.0f / (BB * GG));
        g_done_counter = 0;
    }
}

// ---------------------------------------------------------------------------
extern "C" void kernel_launch(void* const* d_in, const int* in_sizes, int n_in,
                              void* d_out, int out_size)
{
    const float* pred_exist = (const float*)d_in[0];
    const float* pred_pts   = (const float*)d_in[1];
    const float* pred_type  = (const float*)d_in[2];
    const float* gt_points  = (const float*)d_in[4];
    const float* gt_vis     = (const float*)d_in[5];
    const int*   gt_type    = (const int*)d_in[6];
    float* out = (float*)d_out;

    cost_kernel<<<BB * QQ * GG, PP>>>(pred_pts, gt_points, gt_vis, pred_exist);
    hungarian_pair_final_kernel<<<BB, 128>>>(pred_exist, pred_pts, pred_type,
                                             gt_points, gt_vis, gt_type, out);
}

// round 5
// speedup vs baseline: 1.5783x; 1.0209x over previous
#include <cuda_runtime.h>
#include <cuda_bf16.h>
#include <math.h>

#define BB 16
#define QQ 50
#define GG 16
#define PP 64
#define NT 7
#define NSEG (PP - 1)

typedef unsigned long long u64;

// packed f32x2 helpers
#define F2PACK(d, lo, hi)  asm("mov.b64 %0, {%1,%2};" : "=l"(d) : "f"(lo), "f"(hi))
#define F2UNPACK(lo, hi, s) asm("mov.b64 {%0,%1}, %2;" : "=f"(lo), "=f"(hi) : "l"(s))
#define F2FMA(d, a, b, c)  asm("fma.rn.f32x2 %0, %1, %2, %3;" : "=l"(d) : "l"(a), "l"(b), "l"(c))
#define F2MUL(d, a, b)     asm("mul.rn.f32x2 %0, %1, %2;" : "=l"(d) : "l"(a), "l"(b))

// Scratch (device globals; no allocation allowed)
__device__ float g_curve[BB * QQ * GG];
__device__ float g_dir[BB * QQ * GG];
__device__ float g_cost[BB * QQ * GG];
__device__ float g_blk_pair[BB];
__device__ float g_blk_x[BB];
__device__ float g_blk_bce[BB];
__device__ int   g_done_counter;   // zero-init; last block resets each run

// ---------------------------------------------------------------------------
// Kernel A: cost matrix. One block per (b,q,g), 64 threads (one per point).
// p2g / g2p packed into f32x2 lanes.  Segment params stored in shared as
// PRE-PACKED ulonglong2 so LDS.128 delivers f32x2 operands with no MOVs.
//   d^2 - |p|^2 = pa + ab2 * t * (t - 2r),  t = sat(r)
// ---------------------------------------------------------------------------
__global__ __launch_bounds__(PP) void cost_kernel(
    const float* __restrict__ pred_pts,
    const float* __restrict__ gt_pts,
    const float* __restrict__ gt_vis,
    const float* __restrict__ pred_exist)
{
    int blk = blockIdx.x;
    int g = blk % GG;
    int q = (blk / GG) % QQ;
    int b = blk / (GG * QQ);
    int t = threadIdx.x;   // 0..63
    int lane = t & 31, wid = t >> 5;

    __shared__ float2 sP[PP], sG[PP];
    __shared__ float  sV[PP];
    __shared__ ulonglong2 sS0[NSEG];  // (nx2, ny2)
    __shared__ ulonglong2 sS1[NSEG];  // (cr2, bx2)
    __shared__ ulonglong2 sS2[NSEG];  // (by2, cpa2)
    __shared__ u64        sS3[NSEG];  // ab22
    __shared__ float  sTdot[NSEG];
    __shared__ float  sred[5][2];

    const float2* pp = (const float2*)(pred_pts + ((size_t)(b * QQ + q)) * PP * 2);
    const float2* gp = (const float2*)(gt_pts   + ((size_t)(b * GG + g)) * PP * 2);
    float2 myP = pp[t];
    float2 myG = gp[t];
    sP[t] = myP;
    sG[t] = myG;
    float myV = gt_vis[(size_t)(b * GG + g) * PP + t];
    sV[t] = myV;
    __syncthreads();

    if (t < NSEG) {
        float2 aG = sG[t], bG = sG[t + 1];
        float abxg = bG.x - aG.x, abyg = bG.y - aG.y;
        float ab2g = abxg * abxg + abyg * abyg;
        float invg = 1.0f / fmaxf(ab2g, 1e-8f);
        float nxg = abxg * invg, nyg = abyg * invg;
        float crg = -(aG.x * abxg + aG.y * abyg) * invg;

        float2 aP = sP[t], bP = sP[t + 1];
        float abxp = bP.x - aP.x, abyp = bP.y - aP.y;
        float ab2p = abxp * abxp + abyp * abyp;
        float invp = 1.0f / fmaxf(ab2p, 1e-8f);
        float nxp = abxp * invp, nyp = abyp * invp;
        float crp = -(aP.x * abxp + aP.y * abyp) * invp;

        u64 nx2, ny2, cr2, bx2, by2, cpa2, ab22;
        F2PACK(nx2, nxg, nxp);
        F2PACK(ny2, nyg, nyp);
        F2PACK(cr2, crg, crp);
        F2PACK(bx2, -2.0f * aG.x, -2.0f * aP.x);
        F2PACK(by2, -2.0f * aG.y, -2.0f * aP.y);
        F2PACK(cpa2, aG.x * aG.x + aG.y * aG.y, aP.x * aP.x + aP.y * aP.y);
        F2PACK(ab22, ab2g, ab2p);
        sS0[t] = make_ulonglong2(nx2, ny2);
        sS1[t] = make_ulonglong2(cr2, bx2);
        sS2[t] = make_ulonglong2(by2, cpa2);
        sS3[t] = ab22;

        float itg = 1.0f / fmaxf(sqrtf(ab2g), 1e-6f);
        float itp = 1.0f / fmaxf(sqrtf(ab2p), 1e-6f);
        sTdot[t] = (abxp * abxg + abyp * abyg) * itg * itp;
    }
    __syncthreads();

    u64 Px2, Py2, NEG2;
    F2PACK(Px2, myP.x, myG.x);
    F2PACK(Py2, myP.y, myG.y);
    F2PACK(NEG2, -2.0f, -2.0f);

    float mLo = 3.0e38f, mHi = 3.0e38f;

    #pragma unroll 7
    for (int j = 0; j < NSEG; j++) {
        ulonglong2 A = sS0[j];   // nx2, ny2
        ulonglong2 Bv = sS1[j];  // cr2, bx2
        ulonglong2 Cv = sS2[j];  // by2, cpa2
        u64 ab22 = sS3[j];

        u64 r2, pa2, t2, w2, z2, val2;
        F2FMA(r2, Py2, A.y, Bv.x);
        F2FMA(r2, Px2, A.x, r2);
        F2FMA(pa2, Py2, Cv.x, Cv.y);
        F2FMA(pa2, Px2, Bv.y, pa2);
        float rl, rh;
        F2UNPACK(rl, rh, r2);
        float tl = __saturatef(rl), th = __saturatef(rh);
        F2PACK(t2, tl, th);
        F2FMA(w2, r2, NEG2, t2);     // t - 2r
        F2MUL(z2, t2, w2);
        F2FMA(val2, z2, ab22, pa2);
        float vl, vh;
        F2UNPACK(vl, vh, val2);
        mLo = fminf(mLo, vl);
        mHi = fminf(mHi, vh);
    }

    float pp2 = myP.x * myP.x + myP.y * myP.y;
    float gg2 = myG.x * myG.x + myG.y * myG.y;
    float v0 = sqrtf(fmaxf(mLo + pp2, 1e-24f));          // dp2g
    float v1 = sqrtf(fmaxf(mHi + gg2, 1e-24f)) * myV;    // dg2p * vis
    float v2 = myV;
    float v3 = 0.0f, v4 = 0.0f;
    if (t < NSEG) {
        float sv_ = myV * sV[t + 1];
        v3 = (1.0f - sTdot[t]) * sv_;
        v4 = sv_;
    }

    #pragma unroll
    for (int off = 16; off > 0; off >>= 1) {
        v0 += __shfl_down_sync(0xffffffffu, v0, off);
        v1 += __shfl_down_sync(0xffffffffu, v1, off);
        v2 += __shfl_down_sync(0xffffffffu, v2, off);
        v3 += __shfl_down_sync(0xffffffffu, v3, off);
        v4 += __shfl_down_sync(0xffffffffu, v4, off);
    }
    if (lane == 0) {
        sred[0][wid] = v0; sred[1][wid] = v1; sred[2][wid] = v2;
        sred[3][wid] = v3; sred[4][wid] = v4;
    }
    __syncthreads();
    if (t == 0) {
        float s0 = sred[0][0] + sred[0][1];
        float s1 = sred[1][0] + sred[1][1];
        float s2 = sred[2][0] + sred[2][1];
        float s3 = sred[3][0] + sred[3][1];
        float s4 = sred[4][0] + sred[4][1];
        float visS = fmaxf(s2, 1.0f);
        float curve = 0.5f * (s0 * (1.0f / PP) + s1 / visS);
        float dir = s3 / fmaxf(s4, 1.0f);
        int idx = (b * QQ + q) * GG + g;
        g_curve[idx] = curve;
        g_dir[idx] = dir;
        float x = pred_exist[b * QQ + q];
        float sig = 1.0f / (1.0f + expf(-x));
        g_cost[idx] = curve + 0.35f * dir - 0.25f * sig;
    }
}

// ---------------------------------------------------------------------------
// Kernel B: LAPJV Hungarian (warp 0). Per-Dijkstra register caches:
//   r_c = sRow[c] (static during Dijkstra), w_c = sC[r_c][c] - v_c.
// Per step: one REDUX (col in low 6 key bits) + three owner-lane shuffles
// (D, W_js, r_js); h = W_js - D needs no memory. Only remaining LDS is the
// relax row sC[r][c], overlapped with the shuffles.
// ---------------------------------------------------------------------------
__device__ __forceinline__ unsigned okey(float f) {
    unsigned u = __float_as_uint(f);
    return (u & 0x80000000u) ? ~u : (u | 0x80000000u);
}
__device__ __forceinline__ float smooth_l1(float x) {
    float ax = fabsf(x);
    return (ax < 1.0f) ? 0.5f * x * x : ax - 0.5f;
}

__global__ __launch_bounds__(128) void hungarian_pair_final_kernel(
    const float* __restrict__ pred_exist,
    const float* __restrict__ pred_pts,
    const float* __restrict__ pred_type,
    const float* __restrict__ gt_pts,
    const float* __restrict__ gt_vis,
    const int*   __restrict__ gt_type,
    float* __restrict__ out)
{
    int b = blockIdx.x;
    int tid = threadIdx.x;
    int lane = tid & 31, warp = tid >> 5;

    __shared__ float sC[GG][QQ];
    __shared__ int   sRow[QQ];
    __shared__ int   sway[QQ];
    __shared__ int   s_match[GG];
    __shared__ float s_wsum[4];
    __shared__ float s_xsum, s_bce;
    __shared__ int   s_last;
    __shared__ float s_red[128];

    for (int idx = tid; idx < GG * QQ; idx += 128) {
        int qq = idx >> 4, gg = idx & 15;
        sC[gg][qq] = g_cost[(b * QQ + qq) * GG + gg];
    }
    if (tid < QQ) sRow[tid] = -1;
    __syncthreads();

    if (warp == 0) {
        const float INF_F = 1e30f;
        int c0 = lane, c1 = lane + 32;
        bool have1 = (c1 < QQ);
        float v0 = 0.0f, v1 = 0.0f;  // register-resident potentials

        for (int r0 = 0; r0 < GG; ++r0) {
            // per-Dijkstra caches (sRow/potentials static until augmentation)
            int rc0 = sRow[c0];
            int rc1 = have1 ? sRow[c1] : -1;
            float w0 = (rc0 >= 0) ? (sC[rc0][c0] - v0) : 0.0f;
            float w1 = (rc1 >= 0) ? (sC[rc1][c1] - v1) : 0.0f;
            float d0 = sC[r0][c0] - v0;
            float d1 = have1 ? (sC[r0][c1] - v1) : INF_F;
            sway[c0] = -1;
            if (have1) sway[c1] = -1;
            bool sc0 = false, sc1 = false;
            int jf; float D;

            while (true) {
                float cand0 = sc0 ? INF_F : d0;
                float cand1 = sc1 ? INF_F : d1;
                bool pick1 = cand1 < cand0;
                float bval = pick1 ? cand1 : cand0;
                unsigned bcol = pick1 ? (unsigned)c1 : (unsigned)c0;
                unsigned key = (okey(bval) & 0xFFFFFFC0u) | bcol;
                unsigned kmin = __reduce_min_sync(0xffffffffu, key);
                int js = (int)(kmin & 63u);
                int jl = js & 31;
                bool hiSlot = js >= 32;
                float sendD = hiSlot ? d1 : d0;
                float sendW = hiSlot ? w1 : w0;
                int   sendR = hiSlot ? rc1 : rc0;
                D         = __shfl_sync(0xffffffffu, sendD, jl);
                float Wjs = __shfl_sync(0xffffffffu, sendW, jl);
                int   rws = __shfl_sync(0xffffffffu, sendR, jl);
                if (lane == jl) { if (hiSlot) sc1 = true; else sc0 = true; }
                if (rws < 0) { jf = js; break; }
                float h = Wjs - D;   // = sC[rws][js] - v_js - D, no memory
                float a0 = sC[rws][c0] - v0 - h;
                if (!sc0 && a0 < d0) { d0 = a0; sway[c0] = js; }
                if (have1) {
                    float a1 = sC[rws][c1] - v1 - h;
                    if (!sc1 && a1 < d1) { d1 = a1; sway[c1] = js; }
                }
            }
            if (sc0) v0 += d0 - D;
            if (sc1) v1 += d1 - D;
            __syncwarp();
            if (lane == 0) {
                int cur = jf;
                while (true) {
                    int src = sway[cur];
                    if (src < 0) { sRow[cur] = r0; break; }
                    sRow[cur] = sRow[src];
                    cur = src;
                }
            }
            __syncwarp();
        }
        // extract matches
        {
            int r = sRow[c0];
            if (r >= 0) s_match[r] = c0;
            if (have1) { int r2 = sRow[c1]; if (r2 >= 0) s_match[r2] = c1; }
        }
        __syncwarp();
        float xs = (lane < GG) ? pred_exist[b * QQ + s_match[lane]] : 0.0f;
        #pragma unroll
        for (int off = 16; off > 0; off >>= 1) xs += __shfl_down_sync(0xffffffffu, xs, off);
        if (lane == 0) s_xsum = xs;
    } else if (warp == 1) {
        float acc = 0.0f;
        for (int q_ = lane; q_ < QQ; q_ += 32) {
            float x = pred_exist[b * QQ + q_];
            acc += fmaxf(x, 0.0f) + log1pf(expf(-fabsf(x)));
        }
        #pragma unroll
        for (int off = 16; off > 0; off >>= 1) acc += __shfl_down_sync(0xffffffffu, acc, off);
        if (lane == 0) s_bce = acc;
    }
    __syncthreads();

    // ---- Phase 2: pair losses; warp w handles g = 4w..4w+3 ----
    float acc = 0.0f;
    for (int k = 0; k < 4; k++) {
        int g = warp * 4 + k;
        int row = s_match[g];
        const float* pp = pred_pts + (size_t)(b * QQ + row) * PP * 2;
        const float* gp = gt_pts   + (size_t)(b * GG + g) * PP * 2;
        const float* vp = gt_vis   + (size_t)(b * GG + g) * PP;

        float ptsv = 0.0f, viss = 0.0f, smv = 0.0f, cvs = 0.0f;
        #pragma unroll
        for (int h = 0; h < 2; h++) {
            int t = lane + 32 * h;
            float px = pp[2 * t], py = pp[2 * t + 1];
            float gx = gp[2 * t], gy = gp[2 * t + 1];
            float v = vp[t];
            ptsv += (smooth_l1(px - gx) + smooth_l1(py - gy)) * v;
            viss += v;
            if (t >= 1 && t <= PP - 2) {
                float sx = pp[2 * t + 2] - 2.0f * px + pp[2 * t - 2];
                float sy = pp[2 * t + 3] - 2.0f * py + pp[2 * t - 1];
                float mag = sqrtf(fmaxf(sx * sx + sy * sy, 1e-24f));
                float cv = vp[t - 1] * v * vp[t + 1];
                smv += mag * cv;
                cvs += cv;
            }
        }
        #pragma unroll
        for (int off = 16; off > 0; off >>= 1) {
            ptsv += __shfl_down_sync(0xffffffffu, ptsv, off);
            viss += __shfl_down_sync(0xffffffffu, viss, off);
            smv  += __shfl_down_sync(0xffffffffu, smv, off);
            cvs  += __shfl_down_sync(0xffffffffu, cvs, off);
        }
        if (lane == 0) {
            float visS = fmaxf(viss, 1.0f);
            float pts = ptsv / visS;
            float smooth = smv / fmaxf(cvs, 1.0f);
            const float* lg = pred_type + (size_t)(b * QQ + row) * NT;
            int label = gt_type[b * GG + g];
            float mx = lg[0];
            #pragma unroll
            for (int n = 1; n < NT; n++) mx = fmaxf(mx, lg[n]);
            float se = 0.0f;
            #pragma unroll
            for (int n = 0; n < NT; n++) se += expf(lg[n] - mx);
            float ce = mx + logf(se) - lg[label];
            int ci = (b * QQ + row) * GG + g;
            acc += 3.0f * pts + 5.0f * g_curve[ci] + 1.5f * g_dir[ci] +
                   0.25f * smooth + 0.5f * ce;
        }
    }
    if (lane == 0) s_wsum[warp] = acc;
    __syncthreads();

    if (tid == 0) {
        g_blk_pair[b] = s_wsum[0] + s_wsum[1] + s_wsum[2] + s_wsum[3];
        g_blk_x[b] = s_xsum;
        g_blk_bce[b] = s_bce;
        __threadfence();
        int old = atomicAdd(&g_done_counter, 1);
        s_last = (old == BB - 1) ? 1 : 0;
    }
    __syncthreads();
    if (!s_last) return;

    // ---- Phase 3 (last block): combine -> scalar ----
    float pacc = 0.0f, xacc = 0.0f, bacc = 0.0f;
    if (tid < BB) {
        pacc = *((volatile float*)&g_blk_pair[tid]);
        xacc = *((volatile float*)&g_blk_x[tid]);
        bacc = *((volatile float*)&g_blk_bce[tid]);
    }
    s_red[tid] = pacc;
    __syncthreads();
    for (int s = 64; s > 0; s >>= 1) { if (tid < s) s_red[tid] += s_red[tid + s]; __syncthreads(); }
    float pair_sum = s_red[0];
    __syncthreads();
    s_red[tid] = xacc;
    __syncthreads();
    for (int s = 64; s > 0; s >>= 1) { if (tid < s) s_red[tid] += s_red[tid + s]; __syncthreads(); }
    float x_sum = s_red[0];
    __syncthreads();
    s_red[tid] = bacc;
    __syncthreads();
    for (int s = 64; s > 0; s >>= 1) { if (tid < s) s_red[tid] += s_red[tid + s]; __syncthreads(); }
    if (tid == 0) {
        float bce_sum = s_red[0];
        float bce = (bce_sum - x_sum) * (1.0f / (BB * QQ));
        out[0] = 1.5f * bce + pair_sum * (1.0f / (BB * GG));
        g_done_counter = 0;
    }
}

// ---------------------------------------------------------------------------
extern "C" void kernel_launch(void* const* d_in, const int* in_sizes, int n_in,
                              void* d_out, int out_size)
{
    const float* pred_exist = (const float*)d_in[0];
    const float* pred_pts   = (const float*)d_in[1];
    const float* pred_type  = (const float*)d_in[2];
    const float* gt_points  = (const float*)d_in[4];
    const float* gt_vis     = (const float*)d_in[5];
    const int*   gt_type    = (const int*)d_in[6];
    float* out = (float*)d_out;

    cost_kernel<<<BB * QQ * GG, PP>>>(pred_pts, gt_points, gt_vis, pred_exist);
    hungarian_pair_final_kernel<<<BB, 128>>>(pred_exist, pred_pts, pred_type,
                                             gt_points, gt_vis, gt_type, out);
}

// round 6
// speedup vs baseline: 1.5868x; 1.0053x over previous
#include <cuda_runtime.h>
#include <cuda_bf16.h>
#include <math.h>

#define BB 16
#define QQ 50
#define GG 16
#define PP 64
#define NT 7
#define NSEG (PP - 1)

typedef unsigned long long u64;

// packed f32x2 helpers
#define F2PACK(d, lo, hi)  asm("mov.b64 %0, {%1,%2};" : "=l"(d) : "f"(lo), "f"(hi))
#define F2UNPACK(lo, hi, s) asm("mov.b64 {%0,%1}, %2;" : "=f"(lo), "=f"(hi) : "l"(s))
#define F2FMA(d, a, b, c)  asm("fma.rn.f32x2 %0, %1, %2, %3;" : "=l"(d) : "l"(a), "l"(b), "l"(c))
#define F2MUL(d, a, b)     asm("mul.rn.f32x2 %0, %1, %2;" : "=l"(d) : "l"(a), "l"(b))

// Scratch (device globals; no allocation allowed)
__device__ float g_curve[BB * QQ * GG];
__device__ float g_dir[BB * QQ * GG];
__device__ float g_cost[BB * QQ * GG];
__device__ float g_blk_pair[BB];
__device__ float g_blk_x[BB];
__device__ float g_blk_bce[BB];
__device__ int   g_done_counter;   // zero-init; last block resets each run

// ---------------------------------------------------------------------------
// Kernel A: cost matrix. One block per (b,q,g), 64 threads (one per point).
// p2g / g2p packed into f32x2 lanes; segment params pre-packed as ulonglong2.
//   d^2 - |p|^2 = pa + ab2 * t * (t - 2r),  t = sat(r)
// ---------------------------------------------------------------------------
__global__ __launch_bounds__(PP) void cost_kernel(
    const float* __restrict__ pred_pts,
    const float* __restrict__ gt_pts,
    const float* __restrict__ gt_vis,
    const float* __restrict__ pred_exist)
{
    int blk = blockIdx.x;
    int g = blk % GG;
    int q = (blk / GG) % QQ;
    int b = blk / (GG * QQ);
    int t = threadIdx.x;   // 0..63
    int lane = t & 31, wid = t >> 5;

    __shared__ float2 sP[PP], sG[PP];
    __shared__ float  sV[PP];
    __shared__ ulonglong2 sS0[NSEG];  // (nx2, ny2)
    __shared__ ulonglong2 sS1[NSEG];  // (cr2, bx2)
    __shared__ ulonglong2 sS2[NSEG];  // (by2, cpa2)
    __shared__ u64        sS3[NSEG];  // ab22
    __shared__ float  sTdot[NSEG];
    __shared__ float  sred[5][2];

    const float2* pp = (const float2*)(pred_pts + ((size_t)(b * QQ + q)) * PP * 2);
    const float2* gp = (const float2*)(gt_pts   + ((size_t)(b * GG + g)) * PP * 2);
    float2 myP = pp[t];
    float2 myG = gp[t];
    sP[t] = myP;
    sG[t] = myG;
    float myV = gt_vis[(size_t)(b * GG + g) * PP + t];
    sV[t] = myV;
    __syncthreads();

    if (t < NSEG) {
        float2 aG = sG[t], bG = sG[t + 1];
        float abxg = bG.x - aG.x, abyg = bG.y - aG.y;
        float ab2g = abxg * abxg + abyg * abyg;
        float invg = 1.0f / fmaxf(ab2g, 1e-8f);
        float nxg = abxg * invg, nyg = abyg * invg;
        float crg = -(aG.x * abxg + aG.y * abyg) * invg;

        float2 aP = sP[t], bP = sP[t + 1];
        float abxp = bP.x - aP.x, abyp = bP.y - aP.y;
        float ab2p = abxp * abxp + abyp * abyp;
        float invp = 1.0f / fmaxf(ab2p, 1e-8f);
        float nxp = abxp * invp, nyp = abyp * invp;
        float crp = -(aP.x * abxp + aP.y * abyp) * invp;

        u64 nx2, ny2, cr2, bx2, by2, cpa2, ab22;
        F2PACK(nx2, nxg, nxp);
        F2PACK(ny2, nyg, nyp);
        F2PACK(cr2, crg, crp);
        F2PACK(bx2, -2.0f * aG.x, -2.0f * aP.x);
        F2PACK(by2, -2.0f * aG.y, -2.0f * aP.y);
        F2PACK(cpa2, aG.x * aG.x + aG.y * aG.y, aP.x * aP.x + aP.y * aP.y);
        F2PACK(ab22, ab2g, ab2p);
        sS0[t] = make_ulonglong2(nx2, ny2);
        sS1[t] = make_ulonglong2(cr2, bx2);
        sS2[t] = make_ulonglong2(by2, cpa2);
        sS3[t] = ab22;

        float itg = 1.0f / fmaxf(sqrtf(ab2g), 1e-6f);
        float itp = 1.0f / fmaxf(sqrtf(ab2p), 1e-6f);
        sTdot[t] = (abxp * abxg + abyp * abyg) * itg * itp;
    }
    __syncthreads();

    u64 Px2, Py2, NEG2;
    F2PACK(Px2, myP.x, myG.x);
    F2PACK(Py2, myP.y, myG.y);
    F2PACK(NEG2, -2.0f, -2.0f);

    float mLo = 3.0e38f, mHi = 3.0e38f;

    #pragma unroll 7
    for (int j = 0; j < NSEG; j++) {
        ulonglong2 A = sS0[j];   // nx2, ny2
        ulonglong2 Bv = sS1[j];  // cr2, bx2
        ulonglong2 Cv = sS2[j];  // by2, cpa2
        u64 ab22 = sS3[j];

        u64 r2, pa2, t2, w2, z2, val2;
        F2FMA(r2, Py2, A.y, Bv.x);
        F2FMA(r2, Px2, A.x, r2);
        F2FMA(pa2, Py2, Cv.x, Cv.y);
        F2FMA(pa2, Px2, Bv.y, pa2);
        float rl, rh;
        F2UNPACK(rl, rh, r2);
        float tl = __saturatef(rl), th = __saturatef(rh);
        F2PACK(t2, tl, th);
        F2FMA(w2, r2, NEG2, t2);     // t - 2r
        F2MUL(z2, t2, w2);
        F2FMA(val2, z2, ab22, pa2);
        float vl, vh;
        F2UNPACK(vl, vh, val2);
        mLo = fminf(mLo, vl);
        mHi = fminf(mHi, vh);
    }

    float pp2 = myP.x * myP.x + myP.y * myP.y;
    float gg2 = myG.x * myG.x + myG.y * myG.y;
    float v0 = sqrtf(fmaxf(mLo + pp2, 1e-24f));          // dp2g
    float v1 = sqrtf(fmaxf(mHi + gg2, 1e-24f)) * myV;    // dg2p * vis
    float v2 = myV;
    float v3 = 0.0f, v4 = 0.0f;
    if (t < NSEG) {
        float sv_ = myV * sV[t + 1];
        v3 = (1.0f - sTdot[t]) * sv_;
        v4 = sv_;
    }

    #pragma unroll
    for (int off = 16; off > 0; off >>= 1) {
        v0 += __shfl_down_sync(0xffffffffu, v0, off);
        v1 += __shfl_down_sync(0xffffffffu, v1, off);
        v2 += __shfl_down_sync(0xffffffffu, v2, off);
        v3 += __shfl_down_sync(0xffffffffu, v3, off);
        v4 += __shfl_down_sync(0xffffffffu, v4, off);
    }
    if (lane == 0) {
        sred[0][wid] = v0; sred[1][wid] = v1; sred[2][wid] = v2;
        sred[3][wid] = v3; sred[4][wid] = v4;
    }
    __syncthreads();
    if (t == 0) {
        float s0 = sred[0][0] + sred[0][1];
        float s1 = sred[1][0] + sred[1][1];
        float s2 = sred[2][0] + sred[2][1];
        float s3 = sred[3][0] + sred[3][1];
        float s4 = sred[4][0] + sred[4][1];
        float visS = fmaxf(s2, 1.0f);
        float curve = 0.5f * (s0 * (1.0f / PP) + s1 / visS);
        float dir = s3 / fmaxf(s4, 1.0f);
        int idx = (b * QQ + q) * GG + g;
        g_curve[idx] = curve;
        g_dir[idx] = dir;
        float x = pred_exist[b * QQ + q];
        float sig = 1.0f / (1.0f + expf(-x));
        g_cost[idx] = curve + 0.35f * dir - 0.25f * sig;
    }
}

// ---------------------------------------------------------------------------
// Kernel B: LAPJV Hungarian (warp 0) with GREEDY ROW-REDUCTION INIT:
// with v=0, each row grabs its argmin column if free (one REDUX per row,
// complementary slackness holds by construction). Only collided rows
// (~2-3 expected) run the Dijkstra. Dijkstra itself: register caches,
// index-embedded REDUX argmin, owner-lane shuffles (no LDS in chain).
// ---------------------------------------------------------------------------
__device__ __forceinline__ unsigned okey(float f) {
    unsigned u = __float_as_uint(f);
    return (u & 0x80000000u) ? ~u : (u | 0x80000000u);
}
__device__ __forceinline__ float smooth_l1(float x) {
    float ax = fabsf(x);
    return (ax < 1.0f) ? 0.5f * x * x : ax - 0.5f;
}

__global__ __launch_bounds__(128) void hungarian_pair_final_kernel(
    const float* __restrict__ pred_exist,
    const float* __restrict__ pred_pts,
    const float* __restrict__ pred_type,
    const float* __restrict__ gt_pts,
    const float* __restrict__ gt_vis,
    const int*   __restrict__ gt_type,
    float* __restrict__ out)
{
    int b = blockIdx.x;
    int tid = threadIdx.x;
    int lane = tid & 31, warp = tid >> 5;

    __shared__ float sC[GG][QQ];
    __shared__ int   sRow[QQ];
    __shared__ int   sway[QQ];
    __shared__ int   s_match[GG];
    __shared__ float s_wsum[4];
    __shared__ float s_xsum, s_bce;
    __shared__ int   s_last;
    __shared__ float s_red[128];

    for (int idx = tid; idx < GG * QQ; idx += 128) {
        int qq = idx >> 4, gg = idx & 15;
        sC[gg][qq] = g_cost[(b * QQ + qq) * GG + gg];
    }
    if (tid < QQ) sRow[tid] = -1;
    __syncthreads();

    if (warp == 0) {
        const float INF_F = 1e30f;
        int c0 = lane, c1 = lane + 32;
        bool have1 = (c1 < QQ);
        float v0 = 0.0f, v1 = 0.0f;  // register-resident potentials

        // ---- Greedy row reduction (v = 0) ----
        unsigned pending = 0;
        for (int i = 0; i < GG; ++i) {
            float b0 = sC[i][c0];
            float b1 = have1 ? sC[i][c1] : INF_F;
            bool pick1 = b1 < b0;
            float bval = pick1 ? b1 : b0;
            unsigned bcol = pick1 ? (unsigned)c1 : (unsigned)c0;
            unsigned key = (okey(bval) & 0xFFFFFFC0u) | bcol;
            unsigned kmin = __reduce_min_sync(0xffffffffu, key);
            int js = (int)(kmin & 63u);
            if (sRow[js] < 0) {
                if (lane == (js & 31)) sRow[js] = i;
            } else {
                pending |= 1u << i;
            }
            __syncwarp();
        }

        // ---- Dijkstra only for collided rows ----
        while (pending) {
            int r0 = __ffs(pending) - 1;
            pending &= pending - 1;

            int rc0 = sRow[c0];
            int rc1 = have1 ? sRow[c1] : -1;
            float w0 = (rc0 >= 0) ? (sC[rc0][c0] - v0) : 0.0f;
            float w1 = (rc1 >= 0) ? (sC[rc1][c1] - v1) : 0.0f;
            float d0 = sC[r0][c0] - v0;
            float d1 = have1 ? (sC[r0][c1] - v1) : INF_F;
            sway[c0] = -1;
            if (have1) sway[c1] = -1;
            bool sc0 = false, sc1 = false;
            int jf; float D;

            while (true) {
                float cand0 = sc0 ? INF_F : d0;
                float cand1 = sc1 ? INF_F : d1;
                bool pick1 = cand1 < cand0;
                float bval = pick1 ? cand1 : cand0;
                unsigned bcol = pick1 ? (unsigned)c1 : (unsigned)c0;
                unsigned key = (okey(bval) & 0xFFFFFFC0u) | bcol;
                unsigned kmin = __reduce_min_sync(0xffffffffu, key);
                int js = (int)(kmin & 63u);
                int jl = js & 31;
                bool hiSlot = js >= 32;
                float sendD = hiSlot ? d1 : d0;
                float sendW = hiSlot ? w1 : w0;
                int   sendR = hiSlot ? rc1 : rc0;
                D         = __shfl_sync(0xffffffffu, sendD, jl);
                float Wjs = __shfl_sync(0xffffffffu, sendW, jl);
                int   rws = __shfl_sync(0xffffffffu, sendR, jl);
                if (lane == jl) { if (hiSlot) sc1 = true; else sc0 = true; }
                if (rws < 0) { jf = js; break; }
                float h = Wjs - D;   // = sC[rws][js] - v_js - D, no memory
                float a0 = sC[rws][c0] - v0 - h;
                if (!sc0 && a0 < d0) { d0 = a0; sway[c0] = js; }
                if (have1) {
                    float a1 = sC[rws][c1] - v1 - h;
                    if (!sc1 && a1 < d1) { d1 = a1; sway[c1] = js; }
                }
            }
            if (sc0) v0 += d0 - D;
            if (sc1) v1 += d1 - D;
            __syncwarp();
            if (lane == 0) {
                int cur = jf;
                while (true) {
                    int src = sway[cur];
                    if (src < 0) { sRow[cur] = r0; break; }
                    sRow[cur] = sRow[src];
                    cur = src;
                }
            }
            __syncwarp();
        }
        // extract matches
        {
            int r = sRow[c0];
            if (r >= 0) s_match[r] = c0;
            if (have1) { int r2 = sRow[c1]; if (r2 >= 0) s_match[r2] = c1; }
        }
        __syncwarp();
        float xs = (lane < GG) ? pred_exist[b * QQ + s_match[lane]] : 0.0f;
        #pragma unroll
        for (int off = 16; off > 0; off >>= 1) xs += __shfl_down_sync(0xffffffffu, xs, off);
        if (lane == 0) s_xsum = xs;
    } else if (warp == 1) {
        float acc = 0.0f;
        for (int q_ = lane; q_ < QQ; q_ += 32) {
            float x = pred_exist[b * QQ + q_];
            acc += fmaxf(x, 0.0f) + log1pf(expf(-fabsf(x)));
        }
        #pragma unroll
        for (int off = 16; off > 0; off >>= 1) acc += __shfl_down_sync(0xffffffffu, acc, off);
        if (lane == 0) s_bce = acc;
    }
    __syncthreads();

    // ---- Phase 2: pair losses; warp w handles g = 4w..4w+3 ----
    float acc = 0.0f;
    for (int k = 0; k < 4; k++) {
        int g = warp * 4 + k;
        int row = s_match[g];
        const float* pp = pred_pts + (size_t)(b * QQ + row) * PP * 2;
        const float* gp = gt_pts   + (size_t)(b * GG + g) * PP * 2;
        const float* vp = gt_vis   + (size_t)(b * GG + g) * PP;

        float ptsv = 0.0f, viss = 0.0f, smv = 0.0f, cvs = 0.0f;
        #pragma unroll
        for (int h = 0; h < 2; h++) {
            int t = lane + 32 * h;
            float px = pp[2 * t], py = pp[2 * t + 1];
            float gx = gp[2 * t], gy = gp[2 * t + 1];
            float v = vp[t];
            ptsv += (smooth_l1(px - gx) + smooth_l1(py - gy)) * v;
            viss += v;
            if (t >= 1 && t <= PP - 2) {
                float sx = pp[2 * t + 2] - 2.0f * px + pp[2 * t - 2];
                float sy = pp[2 * t + 3] - 2.0f * py + pp[2 * t - 1];
                float mag = sqrtf(fmaxf(sx * sx + sy * sy, 1e-24f));
                float cv = vp[t - 1] * v * vp[t + 1];
                smv += mag * cv;
                cvs += cv;
            }
        }
        #pragma unroll
        for (int off = 16; off > 0; off >>= 1) {
            ptsv += __shfl_down_sync(0xffffffffu, ptsv, off);
            viss += __shfl_down_sync(0xffffffffu, viss, off);
            smv  += __shfl_down_sync(0xffffffffu, smv, off);
            cvs  += __shfl_down_sync(0xffffffffu, cvs, off);
        }
        if (lane == 0) {
            float visS = fmaxf(viss, 1.0f);
            float pts = ptsv / visS;
            float smooth = smv / fmaxf(cvs, 1.0f);
            const float* lg = pred_type + (size_t)(b * QQ + row) * NT;
            int label = gt_type[b * GG + g];
            float mx = lg[0];
            #pragma unroll
            for (int n = 1; n < NT; n++) mx = fmaxf(mx, lg[n]);
            float se = 0.0f;
            #pragma unroll
            for (int n = 0; n < NT; n++) se += expf(lg[n] - mx);
            float ce = mx + logf(se) - lg[label];
            int ci = (b * QQ + row) * GG + g;
            acc += 3.0f * pts + 5.0f * g_curve[ci] + 1.5f * g_dir[ci] +
                   0.25f * smooth + 0.5f * ce;
        }
    }
    if (lane == 0) s_wsum[warp] = acc;
    __syncthreads();

    if (tid == 0) {
        g_blk_pair[b] = s_wsum[0] + s_wsum[1] + s_wsum[2] + s_wsum[3];
        g_blk_x[b] = s_xsum;
        g_blk_bce[b] = s_bce;
        __threadfence();
        int old = atomicAdd(&g_done_counter, 1);
        s_last = (old == BB - 1) ? 1 : 0;
    }
    __syncthreads();
    if (!s_last) return;

    // ---- Phase 3 (last block): combine -> scalar ----
    float pacc = 0.0f, xacc = 0.0f, bacc = 0.0f;
    if (tid < BB) {
        pacc = *((volatile float*)&g_blk_pair[tid]);
        xacc = *((volatile float*)&g_blk_x[tid]);
        bacc = *((volatile float*)&g_blk_bce[tid]);
    }
    s_red[tid] = pacc;
    __syncthreads();
    for (int s = 64; s > 0; s >>= 1) { if (tid < s) s_red[tid] += s_red[tid + s]; __syncthreads(); }
    float pair_sum = s_red[0];
    __syncthreads();
    s_red[tid] = xacc;
    __syncthreads();
    for (int s = 64; s > 0; s >>= 1) { if (tid < s) s_red[tid] += s_red[tid + s]; __syncthreads(); }
    float x_sum = s_red[0];
    __syncthreads();
    s_red[tid] = bacc;
    __syncthreads();
    for (int s = 64; s > 0; s >>= 1) { if (tid < s) s_red[tid] += s_red[tid + s]; __syncthreads(); }
    if (tid == 0) {
        float bce_sum = s_red[0];
        float bce = (bce_sum - x_sum) * (1.0f / (BB * QQ));
        out[0] = 1.5f * bce + pair_sum * (1.0f / (BB * GG));
        g_done_counter = 0;
    }
}

// ---------------------------------------------------------------------------
extern "C" void kernel_launch(void* const* d_in, const int* in_sizes, int n_in,
                              void* d_out, int out_size)
{
    const float* pred_exist = (const float*)d_in[0];
    const float* pred_pts   = (const float*)d_in[1];
    const float* pred_type  = (const float*)d_in[2];
    const float* gt_points  = (const float*)d_in[4];
    const float* gt_vis     = (const float*)d_in[5];
    const int*   gt_type    = (const int*)d_in[6];
    float* out = (float*)d_out;

    cost_kernel<<<BB * QQ * GG, PP>>>(pred_pts, gt_points, gt_vis, pred_exist);
    hungarian_pair_final_kernel<<<BB, 128>>>(pred_exist, pred_pts, pred_type,
                                             gt_points, gt_vis, gt_type, out);
}